// round 13
// baseline (speedup 1.0000x reference)
#include <cuda_runtime.h>
#include <cuda_fp16.h>
#include <cstdint>
#include <math.h>

#define BB 2
#define SS 2048
#define DD 1024
#define HH 16
#define HD 64
#define MM (BB*SS)

// q pre-scale: 1/8 (attention scale) * log2(e)  -> softmax uses ex2
#define QSCL 0.18033688011112042f

// ---------------- scratch ---------------------------------------------------
__device__ __half g_hsh[MM*DD];        // hs fp16 [m][k]
__device__ __half g_wt[4*DD*DD];       // W^T fp16 [n][k] for q,k,v,c
__device__ __half g_qh[BB*HH*SS*HD];   // q fp16 split-head (pre-scaled by QSCL)
__device__ __half g_kh[BB*HH*SS*HD];   // k fp16 split-head
__device__ __half g_vh[BB*HH*SS*HD];   // v fp16 split-head
__device__ __half g_apreh[MM*DD];      // attention out pre-c_proj fp16

// ---------------- helpers ---------------------------------------------------
__device__ __forceinline__ void mma_f16(float* d, const uint32_t* a,
                                        const uint32_t* b) {
    asm volatile("mma.sync.aligned.m16n8k16.row.col.f32.f16.f16.f32 "
        "{%0,%1,%2,%3}, {%4,%5,%6,%7}, {%8,%9}, {%0,%1,%2,%3};"
        : "+f"(d[0]), "+f"(d[1]), "+f"(d[2]), "+f"(d[3])
        : "r"(a[0]), "r"(a[1]), "r"(a[2]), "r"(a[3]), "r"(b[0]), "r"(b[1]));
}
__device__ __forceinline__ void ldsm4(uint32_t* r, uint32_t sa) {
    asm volatile("ldmatrix.sync.aligned.m8n8.x4.shared.b16 {%0,%1,%2,%3}, [%4];"
        : "=r"(r[0]), "=r"(r[1]), "=r"(r[2]), "=r"(r[3]) : "r"(sa));
}
__device__ __forceinline__ void ldsm2(uint32_t& r0, uint32_t& r1, uint32_t sa) {
    asm volatile("ldmatrix.sync.aligned.m8n8.x2.shared.b16 {%0,%1}, [%2];"
        : "=r"(r0), "=r"(r1) : "r"(sa));
}
__device__ __forceinline__ void ldsm2t(uint32_t& r0, uint32_t& r1, uint32_t sa) {
    asm volatile("ldmatrix.sync.aligned.m8n8.x2.trans.shared.b16 {%0,%1}, [%2];"
                 : "=r"(r0), "=r"(r1) : "r"(sa));
}
__device__ __forceinline__ void cp16(uint32_t s, const void* g) {
    asm volatile("cp.async.cg.shared.global [%0], [%1], 16;"
                 :: "r"(s), "l"(g) : "memory");
}
#define CP_COMMIT() asm volatile("cp.async.commit_group;" ::: "memory")
#define CP_WAIT(n)  asm volatile("cp.async.wait_group %0;" :: "n"(n) : "memory")
__device__ __forceinline__ uint32_t pack_h2(float a, float b) {
    __half2 h = __floats2half2_rn(a, b);
    return *(uint32_t*)&h;
}
__device__ __forceinline__ uint32_t sptr(const void* p) {
    return (uint32_t)__cvta_generic_to_shared(p);
}
__device__ __forceinline__ float ex2f(float x) {
    float r;
    asm("ex2.approx.f32 %0, %1;" : "=f"(r) : "f"(x));
    return r;
}
__device__ __forceinline__ void stg2_cs(void* p, float x, float y) {
    asm volatile("st.global.cs.v2.f32 [%0], {%1,%2};"
                 :: "l"(p), "f"(x), "f"(y) : "memory");
}
__device__ __forceinline__ void stg4_cs(void* p, float4 v) {
    asm volatile("st.global.cs.v4.f32 [%0], {%1,%2,%3,%4};"
                 :: "l"(p), "f"(v.x), "f"(v.y), "f"(v.z), "f"(v.w) : "memory");
}

// ---------------------------------------------------------------------------
// conversions
// ---------------------------------------------------------------------------
__global__ __launch_bounds__(256) void conv_h(const float* __restrict__ x,
                                              __half* __restrict__ y)
{
    int i = blockIdx.x * 256 + threadIdx.x;
    float4 v = ((const float4*)x)[i];
    ((uint2*)y)[i] = make_uint2(pack_h2(v.x, v.y), pack_h2(v.z, v.w));
}

__global__ __launch_bounds__(256) void tconv4_h(const float* __restrict__ w0,
                                                const float* __restrict__ w1,
                                                const float* __restrict__ w2,
                                                const float* __restrict__ w3,
                                                __half* __restrict__ WtBase)
{
    __shared__ float tile[32][33];
    int z = blockIdx.z;
    const float* W = (z == 0) ? w0 : (z == 1) ? w1 : (z == 2) ? w2 : w3;
    __half* Wt = WtBase + (size_t)z * DD * DD;
    int tx = threadIdx.x & 31, ty = threadIdx.x >> 5;
    int k0 = blockIdx.y << 5, n0 = blockIdx.x << 5;
    #pragma unroll
    for (int i = 0; i < 4; i++)
        tile[ty + 8*i][tx] = W[(size_t)(k0 + ty + 8*i)*DD + n0 + tx];
    __syncthreads();
    #pragma unroll
    for (int i = 0; i < 4; i++)
        Wt[(size_t)(n0 + ty + 8*i)*DD + k0 + tx] = __float2half(tile[tx][ty + 8*i]);
}

// ---------------------------------------------------------------------------
// fp16 GEMM (as R12): ldmatrix fragments, 3-stage cp.async, 128x128 tiles.
// ---------------------------------------------------------------------------
#define GS_T (128*40)
#define GEMM_SMEM (3*2*GS_T*2)

__device__ __forceinline__ void gemm_body(const __half* __restrict__ A,
                                          const __half* __restrict__ Wt,
                                          const float* __restrict__ bias,
                                          float* __restrict__ outf32,
                                          __half* __restrict__ outh,
                                          int split, int m0, int n0, float os)
{
    extern __shared__ __half hsm[];
    __half* As = hsm;
    __half* Bs = hsm + 3*GS_T;
    int t = threadIdx.x;
    int wid = t >> 5, lane = t & 31;
    int g = lane >> 2, c = lane & 3;
    int warpM = wid >> 2, warpN = wid & 3;

    float acc[4][4][4];
    #pragma unroll
    for (int mi = 0; mi < 4; mi++)
        #pragma unroll
        for (int ni = 0; ni < 4; ni++)
            #pragma unroll
            for (int r = 0; r < 4; r++) acc[mi][ni][r] = 0.0f;

    int lr = t >> 2, lseg = t & 3;
    const __half* Abase = A  + (size_t)(m0 + lr)*DD + lseg*8;
    const __half* Bbase = Wt + (size_t)(n0 + lr)*DD + lseg*8;
    uint32_t sA = sptr(&As[lr*40 + lseg*8]);
    uint32_t sB = sptr(&Bs[lr*40 + lseg*8]);

    int l7 = lane & 7;
    int aRow = warpM*64 + l7 + ((lane >> 3) & 1)*8;
    int aCol = (lane >> 4)*8;
    int bRow = warpN*32 + l7;
    int bCol = ((lane >> 3) & 1)*8;

    #define G_ISSUE(k0c, st) do {                                             \
        cp16(sA + (st)*(GS_T*2),             Abase + (k0c));                  \
        cp16(sA + (st)*(GS_T*2) + 64*40*2,   Abase + (size_t)64*DD + (k0c));  \
        cp16(sB + (st)*(GS_T*2),             Bbase + (k0c));                  \
        cp16(sB + (st)*(GS_T*2) + 64*40*2,   Bbase + (size_t)64*DD + (k0c));  \
        CP_COMMIT(); } while (0)

    G_ISSUE(0, 0);
    G_ISSUE(32, 1);

    for (int cc = 0; cc < 32; cc++) {
        if (cc < 31) CP_WAIT(1); else CP_WAIT(0);
        __syncthreads();
        if (cc + 2 < 32) G_ISSUE((cc+2)*32, (cc+2)%3);

        const __half* Ac = As + (cc%3)*GS_T;
        const __half* Bc = Bs + (cc%3)*GS_T;
        #pragma unroll
        for (int ks = 0; ks < 2; ks++) {
            uint32_t af[4][4], bf[4][2];
            #pragma unroll
            for (int mi = 0; mi < 4; mi++)
                ldsm4(af[mi], sptr(&Ac[(aRow + mi*16)*40 + ks*16 + aCol]));
            #pragma unroll
            for (int ni = 0; ni < 4; ni++)
                ldsm2(bf[ni][0], bf[ni][1],
                      sptr(&Bc[(bRow + ni*8)*40 + ks*16 + bCol]));
            #pragma unroll
            for (int mi = 0; mi < 4; mi++)
                #pragma unroll
                for (int ni = 0; ni < 4; ni++)
                    mma_f16(acc[mi][ni], af[mi], bf[ni]);
        }
    }

    #pragma unroll
    for (int mi = 0; mi < 4; mi++) {
        int row0 = m0 + warpM*64 + mi*16 + g;
        int b_ = row0 >> 11, s0 = row0 & 2047;
        #pragma unroll
        for (int ni = 0; ni < 4; ni++) {
            int col = n0 + warpN*32 + ni*8 + 2*c;
            float b0 = bias[col], b1 = bias[col+1];
            float2 v0 = make_float2(acc[mi][ni][0] + b0, acc[mi][ni][1] + b1);
            float2 v1 = make_float2(acc[mi][ni][2] + b0, acc[mi][ni][3] + b1);
            int h = col >> 6, ho = col & 63;
            if (outf32) {
                if (split) {
                    *(float2*)&outf32[((size_t)(b_*HH + h)*SS + s0)*HD + ho] = v0;
                    *(float2*)&outf32[((size_t)(b_*HH + h)*SS + s0 + 8)*HD + ho] = v1;
                } else {
                    *(float2*)&outf32[(size_t)row0*DD + col] = v0;
                    *(float2*)&outf32[(size_t)(row0+8)*DD + col] = v1;
                }
            }
            if (outh) {
                *(uint32_t*)&outh[((size_t)(b_*HH + h)*SS + s0)*HD + ho] =
                    pack_h2(v0.x*os, v0.y*os);
                *(uint32_t*)&outh[((size_t)(b_*HH + h)*SS + s0 + 8)*HD + ho] =
                    pack_h2(v1.x*os, v1.y*os);
            }
        }
    }
}

__global__ __launch_bounds__(256, 2) void gemm_qkv(const __half* __restrict__ A,
                                                   const __half* __restrict__ wt,
                                                   const float* __restrict__ bq,
                                                   const float* __restrict__ bk,
                                                   const float* __restrict__ bv,
                                                   float* __restrict__ out_k,
                                                   float* __restrict__ out_v,
                                                   __half* __restrict__ qh,
                                                   __half* __restrict__ kh,
                                                   __half* __restrict__ vh)
{
    int z = blockIdx.z;
    const __half* Wt = wt + (size_t)z * DD * DD;
    const float* bias = (z == 0) ? bq : (z == 1) ? bk : bv;
    float* of  = (z == 0) ? nullptr : (z == 1) ? out_k : out_v;
    __half* oh = (z == 0) ? qh : (z == 1) ? kh : vh;
    float os   = (z == 0) ? QSCL : 1.0f;
    gemm_body(A, Wt, bias, of, oh, 1, blockIdx.y << 7, blockIdx.x << 7, os);
}

__global__ __launch_bounds__(256, 2) void gemm_c(const __half* __restrict__ A,
                                                 const __half* __restrict__ Wt,
                                                 const float* __restrict__ bias,
                                                 float* __restrict__ outf32)
{
    gemm_body(A, Wt, bias, outf32, nullptr, 0, blockIdx.y << 7, blockIdx.x << 7, 1.0f);
}

// ---------------------------------------------------------------------------
// Fused attention, restructured:
//  Phase 1: QK + exp (unnormalized) + row sums + PV (P in registers). No
//           gmem stores, no mid-tile syncs.
//  Epilogue: inv = 1/l; scale O; cross-warpN reduce; write apreh (frees O).
//  Phase 2: pure streaming QK + ex2(S + log2 inv) + st.global.cs to attnw.
//           Q fragments in registers, 128-key K stages, no V.
// smem layout (halves; AT_T = 64*72):
//   [0, AT_T)        Q (live whole kernel)
//   [AT_T, 3AT_T)    phase-1 K stages / epilogue "red" floats
//   [3AT_T, 5AT_T)   phase-1 V stages
//   [2AT_T, ...)     epilogue Osm floats (64x65) then phase-2 K stages
//   [2AT_T, 6AT_T)   phase-2 K stages (2 x 128 rows)
// ---------------------------------------------------------------------------
#define AT_T (64*72)
#define FATTN_SMEM (6*AT_T*2)

__global__ __launch_bounds__(256, 2) void fattn(const __half* __restrict__ kin,
                                                const __half* __restrict__ vin,
                                                float* __restrict__ attnw)
{
    extern __shared__ __half hsm[];
    __half* Qs = hsm;

    int bh = blockIdx.y;
    int qtile = gridDim.x - 1 - blockIdx.x;   // heavy tiles first
    int q0 = qtile << 6;
    int t = threadIdx.x;
    int wid = t >> 5, lane = t & 31;
    int g = lane >> 2, c = lane & 3;
    int warpM = wid >> 2, warpN = wid & 3;

    const __half* qb = g_qh + (size_t)bh * SS * HD;
    const __half* kb = kin  + (size_t)bh * SS * HD;
    const __half* vb = vin  + (size_t)bh * SS * HD;
    float*        wb = attnw + (size_t)bh * SS * SS;

    // zero-fill upper triangle strip (streaming stores, overlap with compute)
    {
        float4 z = make_float4(0.f, 0.f, 0.f, 0.f);
        int zr = q0 + (t >> 2);
        for (int col = q0 + 64 + (t & 3)*4; col < SS; col += 16)
            stg4_cs(&wb[(size_t)zr*SS + col], z);
    }

    int lr = t >> 3, lseg = t & 7;
    int l7 = lane & 7;
    int aRow = warpM*32 + l7 + ((lane >> 3) & 1)*8;   // + mi*16
    int aCol = (lane >> 4)*8;                          // + ks*16
    int bRow = warpN*16 + l7;                          // + ni*8
    int bCol = ((lane >> 3) & 1)*8;                    // + ks*16

    // Q load
    uint32_t sQ = sptr(&Qs[lr*72 + lseg*8]);
    cp16(sQ,           &qb[(size_t)(q0 + lr)*HD + lseg*8]);
    cp16(sQ + 32*72*2, &qb[(size_t)(q0 + lr + 32)*HD + lseg*8]);
    CP_COMMIT();

    int nkb = qtile + 1;

    // ---------------- phase 1: QK + exp + sums + PV ----------------
    uint32_t sK = sptr(&hsm[AT_T   + lr*72 + lseg*8]);
    uint32_t sV = sptr(&hsm[3*AT_T + lr*72 + lseg*8]);
    #define KV_ISSUE(kpos0, st) do {                                          \
        cp16(sK + (st)*(AT_T*2),           &kb[(size_t)((kpos0)+lr)*HD + lseg*8]);    \
        cp16(sK + (st)*(AT_T*2) + 32*72*2, &kb[(size_t)((kpos0)+lr+32)*HD + lseg*8]); \
        cp16(sV + (st)*(AT_T*2),           &vb[(size_t)((kpos0)+lr)*HD + lseg*8]);    \
        cp16(sV + (st)*(AT_T*2) + 32*72*2, &vb[(size_t)((kpos0)+lr+32)*HD + lseg*8]); \
        CP_COMMIT(); } while (0)

    float O[2][8][4];
    #pragma unroll
    for (int mi = 0; mi < 2; mi++)
        #pragma unroll
        for (int ni = 0; ni < 8; ni++)
            #pragma unroll
            for (int r = 0; r < 4; r++) O[mi][ni][r] = 0.0f;
    float psum[2][2] = {{0.f,0.f},{0.f,0.f}};

    KV_ISSUE(0, 0);

    for (int kb2 = 0; kb2 < nkb; kb2++) {
        CP_WAIT(0);
        __syncthreads();
        if (kb2 + 1 < nkb) KV_ISSUE((kb2+1) << 6, (kb2+1) & 1);

        const __half* Kc = hsm + AT_T   + (kb2 & 1)*AT_T;
        const __half* Vc = hsm + 3*AT_T + (kb2 & 1)*AT_T;
        int kpos0 = kb2 << 6;

        // QK over hd=64
        float S[2][2][4];
        #pragma unroll
        for (int mi = 0; mi < 2; mi++)
            #pragma unroll
            for (int ni = 0; ni < 2; ni++)
                #pragma unroll
                for (int r = 0; r < 4; r++) S[mi][ni][r] = 0.0f;

        #pragma unroll
        for (int ks = 0; ks < 4; ks++) {
            uint32_t af[2][4], bf[2][2];
            #pragma unroll
            for (int mi = 0; mi < 2; mi++)
                ldsm4(af[mi], sptr(&Qs[(aRow + mi*16)*72 + ks*16 + aCol]));
            #pragma unroll
            for (int ni = 0; ni < 2; ni++)
                ldsm2(bf[ni][0], bf[ni][1],
                      sptr(&Kc[(bRow + ni*8)*72 + ks*16 + bCol]));
            #pragma unroll
            for (int mi = 0; mi < 2; mi++)
                #pragma unroll
                for (int ni = 0; ni < 2; ni++)
                    mma_f16(S[mi][ni], af[mi], bf[ni]);
        }

        // exp (unnormalized), accumulate sums, pack A-fragments
        uint32_t ap[2][4];
        #pragma unroll
        for (int mi = 0; mi < 2; mi++) {
            int row0 = q0 + warpM*32 + mi*16 + g;
            #pragma unroll
            for (int ni = 0; ni < 2; ni++) {
                int key = kpos0 + warpN*16 + ni*8 + 2*c;
                float e00 = (key   <= row0  ) ? ex2f(S[mi][ni][0]) : 0.f;
                float e01 = (key+1 <= row0  ) ? ex2f(S[mi][ni][1]) : 0.f;
                float e10 = (key   <= row0+8) ? ex2f(S[mi][ni][2]) : 0.f;
                float e11 = (key+1 <= row0+8) ? ex2f(S[mi][ni][3]) : 0.f;
                psum[mi][0] += e00 + e01;
                psum[mi][1] += e10 + e11;
                ap[mi][ni*2    ] = pack_h2(e00, e01);
                ap[mi][ni*2 + 1] = pack_h2(e10, e11);
            }
        }

        // PV: this warp's 16-key slice x full hd=64 (no smem P)
        #pragma unroll
        for (int ni = 0; ni < 8; ni++) {
            uint32_t bb[2];
            ldsm2t(bb[0], bb[1],
                   sptr(&Vc[(warpN*16 + (lane & 15))*72 + ni*8]));
            mma_f16(O[0][ni], ap[0], bb);
            mma_f16(O[1][ni], ap[1], bb);
        }
    }
    __syncthreads();

    // ---------------- epilogue: inv, scale O, reduce, write apreh --------
    float* red = (float*)(hsm + AT_T);
    #pragma unroll
    for (int mi = 0; mi < 2; mi++)
        #pragma unroll
        for (int hh = 0; hh < 2; hh++) {
            float v = psum[mi][hh];
            v += __shfl_xor_sync(0xFFFFFFFF, v, 1);
            v += __shfl_xor_sync(0xFFFFFFFF, v, 2);
            psum[mi][hh] = v;
        }
    if (c == 0) {
        #pragma unroll
        for (int mi = 0; mi < 2; mi++)
            #pragma unroll
            for (int hh = 0; hh < 2; hh++) {
                int lrow = warpM*32 + mi*16 + g + hh*8;
                red[lrow*4 + warpN] = psum[mi][hh];
            }
    }
    __syncthreads();
    if (t < 64) {
        float l = red[t*4] + red[t*4+1] + red[t*4+2] + red[t*4+3];
        red[256 + t] = 1.0f / l;
    }
    __syncthreads();

    float L2i[2][2];
    {
        float inv0a, inv1a;
        #pragma unroll
        for (int mi = 0; mi < 2; mi++) {
            int lrow = warpM*32 + mi*16 + g;
            inv0a = red[256 + lrow];
            inv1a = red[256 + lrow + 8];
            L2i[mi][0] = __log2f(inv0a);
            L2i[mi][1] = __log2f(inv1a);
            #pragma unroll
            for (int ni = 0; ni < 8; ni++) {
                O[mi][ni][0] *= inv0a;  O[mi][ni][1] *= inv0a;
                O[mi][ni][2] *= inv1a;  O[mi][ni][3] *= inv1a;
            }
        }
    }
    __syncthreads();

    // cross-warpN O reduction in smem (Osm at 2*AT_T, away from Qs/red)
    float* Osm = (float*)(hsm + 2*AT_T);   // 64 x 65 fp32
    #pragma unroll 1
    for (int wn = 0; wn < 4; wn++) {
        if (warpN == wn) {
            #pragma unroll
            for (int mi = 0; mi < 2; mi++) {
                int rr = warpM*32 + mi*16 + g;
                #pragma unroll
                for (int ni = 0; ni < 8; ni++) {
                    int cc2 = ni*8 + 2*c;
                    if (wn == 0) {
                        Osm[rr*65 + cc2]       = O[mi][ni][0];
                        Osm[rr*65 + cc2 + 1]   = O[mi][ni][1];
                        Osm[(rr+8)*65 + cc2]   = O[mi][ni][2];
                        Osm[(rr+8)*65 + cc2+1] = O[mi][ni][3];
                    } else {
                        Osm[rr*65 + cc2]       += O[mi][ni][0];
                        Osm[rr*65 + cc2 + 1]   += O[mi][ni][1];
                        Osm[(rr+8)*65 + cc2]   += O[mi][ni][2];
                        Osm[(rr+8)*65 + cc2+1] += O[mi][ni][3];
                    }
                }
            }
        }
        __syncthreads();
    }

    {
        int b_ = bh >> 4, h = bh & 15;
        int row = t >> 2, cb = (t & 3) * 16;
        int s0 = q0 + row;
        uint32_t w[8];
        #pragma unroll
        for (int j = 0; j < 8; j++)
            w[j] = pack_h2(Osm[row*65 + cb + 2*j], Osm[row*65 + cb + 2*j + 1]);
        __half* dst = &g_apreh[((size_t)b_*SS + s0)*DD + h*HD + cb];
        *(uint4*)dst       = make_uint4(w[0], w[1], w[2], w[3]);
        *(uint4*)(dst + 8) = make_uint4(w[4], w[5], w[6], w[7]);
    }
    __syncthreads();   // Osm reads done before phase-2 cp.async overwrites

    // ---------------- phase 2: streaming QK + store ----------------
    // Q fragments hoisted (Qs still intact)
    uint32_t qf[4][2][4];
    #pragma unroll
    for (int ks = 0; ks < 4; ks++)
        #pragma unroll
        for (int mi = 0; mi < 2; mi++)
            ldsm4(qf[ks][mi], sptr(&Qs[(aRow + mi*16)*72 + ks*16 + aCol]));

    int nkb128 = (nkb + 1) >> 1;
    uint32_t sK2 = sptr(&hsm[2*AT_T + lr*72 + lseg*8]);
    #define K2_ISSUE(kpos0, st) do {                                          \
        _Pragma("unroll")                                                     \
        for (int i = 0; i < 4; i++)                                           \
            cp16(sK2 + (st)*(4*AT_T) + i*(32*72*2),                           \
                 &kb[(size_t)((kpos0) + lr + 32*i)*HD + lseg*8]);             \
        CP_COMMIT(); } while (0)

    K2_ISSUE(0, 0);

    for (int j = 0; j < nkb128; j++) {
        CP_WAIT(0);
        __syncthreads();
        if (j + 1 < nkb128) K2_ISSUE((j+1)*128, (j+1) & 1);

        const __half* Kst = hsm + 2*AT_T + (j & 1)*(2*AT_T);

        #pragma unroll
        for (int sb = 0; sb < 2; sb++) {
            if (j*2 + sb >= nkb) break;
            const __half* Kc = Kst + sb*(64*72);
            int kpos0 = (j*2 + sb) << 6;

            float S[2][2][4];
            #pragma unroll
            for (int mi = 0; mi < 2; mi++)
                #pragma unroll
                for (int ni = 0; ni < 2; ni++)
                    #pragma unroll
                    for (int r = 0; r < 4; r++) S[mi][ni][r] = 0.0f;

            #pragma unroll
            for (int ks = 0; ks < 4; ks++) {
                uint32_t bf[2][2];
                #pragma unroll
                for (int ni = 0; ni < 2; ni++)
                    ldsm2(bf[ni][0], bf[ni][1],
                          sptr(&Kc[(bRow + ni*8)*72 + ks*16 + bCol]));
                #pragma unroll
                for (int mi = 0; mi < 2; mi++)
                    #pragma unroll
                    for (int ni = 0; ni < 2; ni++)
                        mma_f16(S[mi][ni], qf[ks][mi], bf[ni]);
            }

            #pragma unroll
            for (int mi = 0; mi < 2; mi++) {
                int lrow = warpM*32 + mi*16 + g;
                int row0 = q0 + lrow;
                float L0 = L2i[mi][0], L1 = L2i[mi][1];
                #pragma unroll
                for (int ni = 0; ni < 2; ni++) {
                    int key = kpos0 + warpN*16 + ni*8 + 2*c;
                    float e00 = (key   <= row0  ) ? ex2f(S[mi][ni][0] + L0) : 0.f;
                    float e01 = (key+1 <= row0  ) ? ex2f(S[mi][ni][1] + L0) : 0.f;
                    float e10 = (key   <= row0+8) ? ex2f(S[mi][ni][2] + L1) : 0.f;
                    float e11 = (key+1 <= row0+8) ? ex2f(S[mi][ni][3] + L1) : 0.f;
                    stg2_cs(&wb[(size_t)row0*SS + key],     e00, e01);
                    stg2_cs(&wb[(size_t)(row0+8)*SS + key], e10, e11);
                }
            }
        }
    }
}

// ---------------------------------------------------------------------------
extern "C" void kernel_launch(void* const* d_in, const int* in_sizes, int n_in,
                              void* d_out, int out_size)
{
    const float* hs = (const float*)d_in[0];
    const float* wq = (const float*)d_in[1];
    const float* bq = (const float*)d_in[2];
    const float* wk = (const float*)d_in[3];
    const float* bk = (const float*)d_in[4];
    const float* wv = (const float*)d_in[5];
    const float* bv = (const float*)d_in[6];
    const float* wc = (const float*)d_in[7];
    const float* bc = (const float*)d_in[8];

    float* out      = (float*)d_out;
    float* out_attn = out;                                   // [B,S,D]
    float* out_w    = out + (size_t)BB*SS*DD;                // [B,H,S,S]
    float* out_k    = out_w + (size_t)BB*HH*SS*SS;           // [B,H,S,hd]
    float* out_v    = out_k + (size_t)BB*HH*SS*HD;           // [B,H,S,hd]

    __half *hsh, *wt, *qh, *kh, *vh, *apreh;
    cudaGetSymbolAddress((void**)&hsh,   g_hsh);
    cudaGetSymbolAddress((void**)&wt,    g_wt);
    cudaGetSymbolAddress((void**)&qh,    g_qh);
    cudaGetSymbolAddress((void**)&kh,    g_kh);
    cudaGetSymbolAddress((void**)&vh,    g_vh);
    cudaGetSymbolAddress((void**)&apreh, g_apreh);

    cudaFuncSetAttribute(gemm_qkv,
                         cudaFuncAttributeMaxDynamicSharedMemorySize, GEMM_SMEM);
    cudaFuncSetAttribute(gemm_c,
                         cudaFuncAttributeMaxDynamicSharedMemorySize, GEMM_SMEM);
    cudaFuncSetAttribute(fattn,
                         cudaFuncAttributeMaxDynamicSharedMemorySize, FATTN_SMEM);

    conv_h<<<(MM*DD/4)/256, 256>>>(hs, hsh);
    tconv4_h<<<dim3(DD/32, DD/32, 4), 256>>>(wq, wk, wv, wc, wt);

    gemm_qkv<<<dim3(DD/128, MM/128, 3), 256, GEMM_SMEM>>>(
        hsh, wt, bq, bk, bv, out_k, out_v, qh, kh, vh);

    fattn<<<dim3(SS/64, BB*HH), 256, FATTN_SMEM>>>(kh, vh, out_w);

    gemm_c<<<dim3(DD/128, MM/128), 256, GEMM_SMEM>>>(
        apreh, wt + 3*(size_t)DD*DD, bc, out_attn);
}

// round 15
// speedup vs baseline: 1.5654x; 1.5654x over previous
#include <cuda_runtime.h>
#include <cuda_fp16.h>
#include <cstdint>
#include <math.h>

#define BB 2
#define SS 2048
#define DD 1024
#define HH 16
#define HD 64
#define MM (BB*SS)

// q pre-scale: 1/8 (attention scale) * log2(e)  -> softmax uses ex2
#define QSCL 0.18033688011112042f

// ---------------- scratch ---------------------------------------------------
__device__ __half g_hsh[MM*DD];        // hs fp16 [m][k]
__device__ __half g_wt[4*DD*DD];       // W^T fp16 [n][k] for q,k,v,c
__device__ __half g_qh[BB*HH*SS*HD];   // q fp16 split-head (pre-scaled by QSCL)
__device__ __half g_kh[BB*HH*SS*HD];   // k fp16 split-head
__device__ __half g_vh[BB*HH*SS*HD];   // v fp16 split-head
__device__ __half g_apreh[MM*DD];      // attention out pre-c_proj fp16

// ---------------- helpers ---------------------------------------------------
__device__ __forceinline__ void mma_f16(float* d, const uint32_t* a,
                                        const uint32_t* b) {
    asm volatile("mma.sync.aligned.m16n8k16.row.col.f32.f16.f16.f32 "
        "{%0,%1,%2,%3}, {%4,%5,%6,%7}, {%8,%9}, {%0,%1,%2,%3};"
        : "+f"(d[0]), "+f"(d[1]), "+f"(d[2]), "+f"(d[3])
        : "r"(a[0]), "r"(a[1]), "r"(a[2]), "r"(a[3]), "r"(b[0]), "r"(b[1]));
}
__device__ __forceinline__ void ldsm4(uint32_t* r, uint32_t sa) {
    asm volatile("ldmatrix.sync.aligned.m8n8.x4.shared.b16 {%0,%1,%2,%3}, [%4];"
        : "=r"(r[0]), "=r"(r[1]), "=r"(r[2]), "=r"(r[3]) : "r"(sa));
}
__device__ __forceinline__ void ldsm2(uint32_t& r0, uint32_t& r1, uint32_t sa) {
    asm volatile("ldmatrix.sync.aligned.m8n8.x2.shared.b16 {%0,%1}, [%2];"
        : "=r"(r0), "=r"(r1) : "r"(sa));
}
__device__ __forceinline__ void ldsm2t(uint32_t& r0, uint32_t& r1, uint32_t sa) {
    asm volatile("ldmatrix.sync.aligned.m8n8.x2.trans.shared.b16 {%0,%1}, [%2];"
                 : "=r"(r0), "=r"(r1) : "r"(sa));
}
__device__ __forceinline__ void cp16(uint32_t s, const void* g) {
    asm volatile("cp.async.cg.shared.global [%0], [%1], 16;"
                 :: "r"(s), "l"(g) : "memory");
}
#define CP_COMMIT() asm volatile("cp.async.commit_group;" ::: "memory")
#define CP_WAIT(n)  asm volatile("cp.async.wait_group %0;" :: "n"(n) : "memory")
__device__ __forceinline__ uint32_t pack_h2(float a, float b) {
    __half2 h = __floats2half2_rn(a, b);
    return *(uint32_t*)&h;
}
__device__ __forceinline__ uint32_t sptr(const void* p) {
    return (uint32_t)__cvta_generic_to_shared(p);
}
__device__ __forceinline__ float ex2f(float x) {
    float r;
    asm("ex2.approx.f32 %0, %1;" : "=f"(r) : "f"(x));
    return r;
}

// ---------------------------------------------------------------------------
// conversions
// ---------------------------------------------------------------------------
__global__ __launch_bounds__(256) void conv_h(const float* __restrict__ x,
                                              __half* __restrict__ y)
{
    int i = blockIdx.x * 256 + threadIdx.x;
    float4 v = ((const float4*)x)[i];
    ((uint2*)y)[i] = make_uint2(pack_h2(v.x, v.y), pack_h2(v.z, v.w));
}

__global__ __launch_bounds__(256) void tconv4_h(const float* __restrict__ w0,
                                                const float* __restrict__ w1,
                                                const float* __restrict__ w2,
                                                const float* __restrict__ w3,
                                                __half* __restrict__ WtBase)
{
    __shared__ float tile[32][33];
    int z = blockIdx.z;
    const float* W = (z == 0) ? w0 : (z == 1) ? w1 : (z == 2) ? w2 : w3;
    __half* Wt = WtBase + (size_t)z * DD * DD;
    int tx = threadIdx.x & 31, ty = threadIdx.x >> 5;
    int k0 = blockIdx.y << 5, n0 = blockIdx.x << 5;
    #pragma unroll
    for (int i = 0; i < 4; i++)
        tile[ty + 8*i][tx] = W[(size_t)(k0 + ty + 8*i)*DD + n0 + tx];
    __syncthreads();
    #pragma unroll
    for (int i = 0; i < 4; i++)
        Wt[(size_t)(n0 + ty + 8*i)*DD + k0 + tx] = __float2half(tile[tx][ty + 8*i]);
}

// ---------------------------------------------------------------------------
// fp16 GEMM: ldmatrix fragments, 3-stage cp.async, 128x128 tiles.
// ---------------------------------------------------------------------------
#define GS_T (128*40)
#define GEMM_SMEM (3*2*GS_T*2)

__device__ __forceinline__ void gemm_body(const __half* __restrict__ A,
                                          const __half* __restrict__ Wt,
                                          const float* __restrict__ bias,
                                          float* __restrict__ outf32,
                                          __half* __restrict__ outh,
                                          int split, int m0, int n0, float os)
{
    extern __shared__ __half hsm[];
    __half* As = hsm;
    __half* Bs = hsm + 3*GS_T;
    int t = threadIdx.x;
    int wid = t >> 5, lane = t & 31;
    int g = lane >> 2, c = lane & 3;
    int warpM = wid >> 2, warpN = wid & 3;

    float acc[4][4][4];
    #pragma unroll
    for (int mi = 0; mi < 4; mi++)
        #pragma unroll
        for (int ni = 0; ni < 4; ni++)
            #pragma unroll
            for (int r = 0; r < 4; r++) acc[mi][ni][r] = 0.0f;

    int lr = t >> 2, lseg = t & 3;
    const __half* Abase = A  + (size_t)(m0 + lr)*DD + lseg*8;
    const __half* Bbase = Wt + (size_t)(n0 + lr)*DD + lseg*8;
    uint32_t sA = sptr(&As[lr*40 + lseg*8]);
    uint32_t sB = sptr(&Bs[lr*40 + lseg*8]);

    int l7 = lane & 7;
    int aRow = warpM*64 + l7 + ((lane >> 3) & 1)*8;
    int aCol = (lane >> 4)*8;
    int bRow = warpN*32 + l7;
    int bCol = ((lane >> 3) & 1)*8;

    #define G_ISSUE(k0c, st) do {                                             \
        cp16(sA + (st)*(GS_T*2),             Abase + (k0c));                  \
        cp16(sA + (st)*(GS_T*2) + 64*40*2,   Abase + (size_t)64*DD + (k0c));  \
        cp16(sB + (st)*(GS_T*2),             Bbase + (k0c));                  \
        cp16(sB + (st)*(GS_T*2) + 64*40*2,   Bbase + (size_t)64*DD + (k0c));  \
        CP_COMMIT(); } while (0)

    G_ISSUE(0, 0);
    G_ISSUE(32, 1);

    for (int cc = 0; cc < 32; cc++) {
        if (cc < 31) CP_WAIT(1); else CP_WAIT(0);
        __syncthreads();
        if (cc + 2 < 32) G_ISSUE((cc+2)*32, (cc+2)%3);

        const __half* Ac = As + (cc%3)*GS_T;
        const __half* Bc = Bs + (cc%3)*GS_T;
        #pragma unroll
        for (int ks = 0; ks < 2; ks++) {
            uint32_t af[4][4], bf[4][2];
            #pragma unroll
            for (int mi = 0; mi < 4; mi++)
                ldsm4(af[mi], sptr(&Ac[(aRow + mi*16)*40 + ks*16 + aCol]));
            #pragma unroll
            for (int ni = 0; ni < 4; ni++)
                ldsm2(bf[ni][0], bf[ni][1],
                      sptr(&Bc[(bRow + ni*8)*40 + ks*16 + bCol]));
            #pragma unroll
            for (int mi = 0; mi < 4; mi++)
                #pragma unroll
                for (int ni = 0; ni < 4; ni++)
                    mma_f16(acc[mi][ni], af[mi], bf[ni]);
        }
    }

    #pragma unroll
    for (int mi = 0; mi < 4; mi++) {
        int row0 = m0 + warpM*64 + mi*16 + g;
        int b_ = row0 >> 11, s0 = row0 & 2047;
        #pragma unroll
        for (int ni = 0; ni < 4; ni++) {
            int col = n0 + warpN*32 + ni*8 + 2*c;
            float b0 = bias[col], b1 = bias[col+1];
            float2 v0 = make_float2(acc[mi][ni][0] + b0, acc[mi][ni][1] + b1);
            float2 v1 = make_float2(acc[mi][ni][2] + b0, acc[mi][ni][3] + b1);
            int h = col >> 6, ho = col & 63;
            if (outf32) {
                if (split) {
                    *(float2*)&outf32[((size_t)(b_*HH + h)*SS + s0)*HD + ho] = v0;
                    *(float2*)&outf32[((size_t)(b_*HH + h)*SS + s0 + 8)*HD + ho] = v1;
                } else {
                    *(float2*)&outf32[(size_t)row0*DD + col] = v0;
                    *(float2*)&outf32[(size_t)(row0+8)*DD + col] = v1;
                }
            }
            if (outh) {
                *(uint32_t*)&outh[((size_t)(b_*HH + h)*SS + s0)*HD + ho] =
                    pack_h2(v0.x*os, v0.y*os);
                *(uint32_t*)&outh[((size_t)(b_*HH + h)*SS + s0 + 8)*HD + ho] =
                    pack_h2(v1.x*os, v1.y*os);
            }
        }
    }
}

__global__ __launch_bounds__(256, 2) void gemm_qkv(const __half* __restrict__ A,
                                                   const __half* __restrict__ wt,
                                                   const float* __restrict__ bq,
                                                   const float* __restrict__ bk,
                                                   const float* __restrict__ bv,
                                                   float* __restrict__ out_k,
                                                   float* __restrict__ out_v,
                                                   __half* __restrict__ qh,
                                                   __half* __restrict__ kh,
                                                   __half* __restrict__ vh)
{
    int z = blockIdx.z;
    const __half* Wt = wt + (size_t)z * DD * DD;
    const float* bias = (z == 0) ? bq : (z == 1) ? bk : bv;
    float* of  = (z == 0) ? nullptr : (z == 1) ? out_k : out_v;
    __half* oh = (z == 0) ? qh : (z == 1) ? kh : vh;
    float os   = (z == 0) ? QSCL : 1.0f;
    gemm_body(A, Wt, bias, of, oh, 1, blockIdx.y << 7, blockIdx.x << 7, os);
}

__global__ __launch_bounds__(256, 2) void gemm_c(const __half* __restrict__ A,
                                                 const __half* __restrict__ Wt,
                                                 const float* __restrict__ bias,
                                                 float* __restrict__ outf32)
{
    gemm_body(A, Wt, bias, outf32, nullptr, 0, blockIdx.y << 7, blockIdx.x << 7, 1.0f);
}

// ---------------------------------------------------------------------------
// Fused attention (R12 structure + causal-mask specialization):
//  Phase 1: denominators. 128-key K tiles, Q frags hoisted; only the
//           diagonal k-block pays mask predicates.
//  Phase 2: normalized attnw + PV; S->A register reuse; stores interleaved
//           with PV compute; diagonal block specialized.
// ---------------------------------------------------------------------------
#define AT_T (64*72)
#define FATTN_SMEM (5*AT_T*2)

__global__ __launch_bounds__(256, 2) void fattn(const __half* __restrict__ kin,
                                                const __half* __restrict__ vin,
                                                float* __restrict__ attnw)
{
    extern __shared__ __half hsm[];
    __half* Qs = hsm;                      // 64x72

    int bh = blockIdx.y;
    int qtile = gridDim.x - 1 - blockIdx.x;   // heavy tiles first
    int q0 = qtile << 6;
    int t = threadIdx.x;
    int wid = t >> 5, lane = t & 31;
    int g = lane >> 2, c = lane & 3;
    int warpM = wid >> 2, warpN = wid & 3;

    const __half* qb = g_qh + (size_t)bh * SS * HD;
    const __half* kb = kin  + (size_t)bh * SS * HD;
    const __half* vb = vin  + (size_t)bh * SS * HD;
    float*        wb = attnw + (size_t)bh * SS * SS;

    // zero-fill upper triangle strip (overlaps with compute)
    {
        float4 z = make_float4(0.f, 0.f, 0.f, 0.f);
        int zr = q0 + (t >> 2);
        for (int col = q0 + 64 + (t & 3)*4; col < SS; col += 16)
            *(float4*)&wb[(size_t)zr*SS + col] = z;
    }

    int lr = t >> 3, lseg = t & 7;
    int l7 = lane & 7;
    int aRow = warpM*32 + l7 + ((lane >> 3) & 1)*8;   // + mi*16
    int aCol = (lane >> 4)*8;                          // + ks*16
    int bRow = warpN*16 + l7;                          // + ni*8
    int bCol = ((lane >> 3) & 1)*8;                    // + ks*16

    // Q load
    uint32_t sQ = sptr(&Qs[lr*72 + lseg*8]);
    cp16(sQ,           &qb[(size_t)(q0 + lr)*HD + lseg*8]);
    cp16(sQ + 32*72*2, &qb[(size_t)(q0 + lr + 32)*HD + lseg*8]);
    CP_COMMIT();

    int nkb = qtile + 1;
    int nkb128 = (nkb + 1) >> 1;

    // phase-1 stage bases (128 rows each)
    uint32_t sK1 = sptr(&hsm[AT_T + lr*72 + lseg*8]);
    #define K128_ISSUE(kpos0, st) do {                                        \
        _Pragma("unroll")                                                     \
        for (int i = 0; i < 4; i++)                                           \
            cp16(sK1 + (st)*(2*AT_T*2) + i*(32*72*2),                         \
                 &kb[(size_t)((kpos0) + lr + 32*i)*HD + lseg*8]);             \
        CP_COMMIT(); } while (0)

    K128_ISSUE(0, 0);
    CP_WAIT(0);
    __syncthreads();

    // hoist Q fragments for phase 1
    uint32_t qf[4][2][4];
    #pragma unroll
    for (int ks = 0; ks < 4; ks++)
        #pragma unroll
        for (int mi = 0; mi < 2; mi++)
            ldsm4(qf[ks][mi], sptr(&Qs[(aRow + mi*16)*72 + ks*16 + aCol]));

    if (nkb128 > 1) K128_ISSUE(128, 1);

    float psum[2][2] = {{0.f,0.f},{0.f,0.f}};

    for (int j = 0; j < nkb128; j++) {
        if (j > 0) {
            CP_WAIT(0);
            __syncthreads();
            if (j + 1 < nkb128) K128_ISSUE((j+1)*128, (j+1) & 1);
        }
        const __half* Kst = hsm + AT_T + (j & 1)*(2*AT_T);

        #pragma unroll
        for (int sb = 0; sb < 2; sb++) {
            int kb2 = j*2 + sb;
            if (kb2 >= nkb) break;
            const __half* Kc = Kst + sb*(64*72);
            int kpos0 = kb2 << 6;
            bool diag = (kb2 == nkb - 1);

            float S[2][2][4];
            #pragma unroll
            for (int mi = 0; mi < 2; mi++)
                #pragma unroll
                for (int ni = 0; ni < 2; ni++)
                    #pragma unroll
                    for (int r = 0; r < 4; r++) S[mi][ni][r] = 0.0f;

            #pragma unroll
            for (int ks = 0; ks < 4; ks++) {
                uint32_t bf[2][2];
                #pragma unroll
                for (int ni = 0; ni < 2; ni++)
                    ldsm2(bf[ni][0], bf[ni][1],
                          sptr(&Kc[(bRow + ni*8)*72 + ks*16 + bCol]));
                #pragma unroll
                for (int mi = 0; mi < 2; mi++)
                    #pragma unroll
                    for (int ni = 0; ni < 2; ni++)
                        mma_f16(S[mi][ni], qf[ks][mi], bf[ni]);
            }

            if (!diag) {
                #pragma unroll
                for (int mi = 0; mi < 2; mi++)
                    #pragma unroll
                    for (int ni = 0; ni < 2; ni++) {
                        psum[mi][0] += ex2f(S[mi][ni][0]) + ex2f(S[mi][ni][1]);
                        psum[mi][1] += ex2f(S[mi][ni][2]) + ex2f(S[mi][ni][3]);
                    }
            } else {
                #pragma unroll
                for (int mi = 0; mi < 2; mi++) {
                    int row0 = q0 + warpM*32 + mi*16 + g;
                    #pragma unroll
                    for (int ni = 0; ni < 2; ni++) {
                        int key = kpos0 + warpN*16 + ni*8 + 2*c;
                        psum[mi][0] += ((key   <= row0  ) ? ex2f(S[mi][ni][0]) : 0.f)
                                     + ((key+1 <= row0  ) ? ex2f(S[mi][ni][1]) : 0.f);
                        psum[mi][1] += ((key   <= row0+8) ? ex2f(S[mi][ni][2]) : 0.f)
                                     + ((key+1 <= row0+8) ? ex2f(S[mi][ni][3]) : 0.f);
                    }
                }
            }
        }
    }
    __syncthreads();

    // reduce -> log2(1/l)
    float* red = (float*)(hsm + AT_T);
    #pragma unroll
    for (int mi = 0; mi < 2; mi++)
        #pragma unroll
        for (int hh = 0; hh < 2; hh++) {
            float v = psum[mi][hh];
            v += __shfl_xor_sync(0xFFFFFFFF, v, 1);
            v += __shfl_xor_sync(0xFFFFFFFF, v, 2);
            psum[mi][hh] = v;
        }
    if (c == 0) {
        #pragma unroll
        for (int mi = 0; mi < 2; mi++)
            #pragma unroll
            for (int hh = 0; hh < 2; hh++) {
                int lrow = warpM*32 + mi*16 + g + hh*8;
                red[lrow*4 + warpN] = psum[mi][hh];
            }
    }
    __syncthreads();
    if (t < 64) {
        float l = red[t*4] + red[t*4+1] + red[t*4+2] + red[t*4+3];
        red[256 + t] = 1.0f / l;
    }
    __syncthreads();

    float L2i[2][2];
    #pragma unroll
    for (int mi = 0; mi < 2; mi++) {
        int lrow = warpM*32 + mi*16 + g;
        L2i[mi][0] = __log2f(red[256 + lrow]);
        L2i[mi][1] = __log2f(red[256 + lrow + 8]);
    }
    __syncthreads();   // before phase-2 cp.async overwrites red region

    // ---------------- phase 2: weights + PV ----------------
    uint32_t sK2 = sptr(&hsm[AT_T   + lr*72 + lseg*8]);
    uint32_t sV2 = sptr(&hsm[3*AT_T + lr*72 + lseg*8]);
    #define KV_ISSUE(kpos0, st) do {                                          \
        cp16(sK2 + (st)*(AT_T*2),           &kb[(size_t)((kpos0)+lr)*HD + lseg*8]);    \
        cp16(sK2 + (st)*(AT_T*2) + 32*72*2, &kb[(size_t)((kpos0)+lr+32)*HD + lseg*8]); \
        cp16(sV2 + (st)*(AT_T*2),           &vb[(size_t)((kpos0)+lr)*HD + lseg*8]);    \
        cp16(sV2 + (st)*(AT_T*2) + 32*72*2, &vb[(size_t)((kpos0)+lr+32)*HD + lseg*8]); \
        CP_COMMIT(); } while (0)

    float O[2][8][4];
    #pragma unroll
    for (int mi = 0; mi < 2; mi++)
        #pragma unroll
        for (int ni = 0; ni < 8; ni++)
            #pragma unroll
            for (int r = 0; r < 4; r++) O[mi][ni][r] = 0.0f;

    KV_ISSUE(0, 0);

    for (int kb2 = 0; kb2 < nkb; kb2++) {
        CP_WAIT(0);
        __syncthreads();
        if (kb2 + 1 < nkb) KV_ISSUE((kb2+1) << 6, (kb2+1) & 1);

        const __half* Kc = hsm + AT_T   + (kb2 & 1)*AT_T;
        const __half* Vc = hsm + 3*AT_T + (kb2 & 1)*AT_T;
        int kpos0 = kb2 << 6;
        bool diag = (kb2 == nkb - 1);

        float S[2][2][4];
        #pragma unroll
        for (int mi = 0; mi < 2; mi++)
            #pragma unroll
            for (int ni = 0; ni < 2; ni++)
                #pragma unroll
                for (int r = 0; r < 4; r++) S[mi][ni][r] = 0.0f;

        #pragma unroll
        for (int ks = 0; ks < 4; ks++) {
            uint32_t af[2][4], bf[2][2];
            #pragma unroll
            for (int mi = 0; mi < 2; mi++)
                ldsm4(af[mi], sptr(&Qs[(aRow + mi*16)*72 + ks*16 + aCol]));
            #pragma unroll
            for (int ni = 0; ni < 2; ni++)
                ldsm2(bf[ni][0], bf[ni][1],
                      sptr(&Kc[(bRow + ni*8)*72 + ks*16 + bCol]));
            #pragma unroll
            for (int mi = 0; mi < 2; mi++)
                #pragma unroll
                for (int ni = 0; ni < 2; ni++)
                    mma_f16(S[mi][ni], af[mi], bf[ni]);
        }

        // normalized weights; store attnw; pack A-fragments
        uint32_t ap[2][4];
        if (!diag) {
            #pragma unroll
            for (int mi = 0; mi < 2; mi++) {
                int lrow = warpM*32 + mi*16 + g;
                int row0 = q0 + lrow;
                float L0 = L2i[mi][0], L1 = L2i[mi][1];
                #pragma unroll
                for (int ni = 0; ni < 2; ni++) {
                    int key = kpos0 + warpN*16 + ni*8 + 2*c;
                    float e00 = ex2f(S[mi][ni][0] + L0);
                    float e01 = ex2f(S[mi][ni][1] + L0);
                    float e10 = ex2f(S[mi][ni][2] + L1);
                    float e11 = ex2f(S[mi][ni][3] + L1);
                    *(float2*)&wb[(size_t)row0*SS + key]     = make_float2(e00, e01);
                    *(float2*)&wb[(size_t)(row0+8)*SS + key] = make_float2(e10, e11);
                    ap[mi][ni*2    ] = pack_h2(e00, e01);
                    ap[mi][ni*2 + 1] = pack_h2(e10, e11);
                }
            }
        } else {
            #pragma unroll
            for (int mi = 0; mi < 2; mi++) {
                int lrow = warpM*32 + mi*16 + g;
                int row0 = q0 + lrow;
                float L0 = L2i[mi][0], L1 = L2i[mi][1];
                #pragma unroll
                for (int ni = 0; ni < 2; ni++) {
                    int key = kpos0 + warpN*16 + ni*8 + 2*c;
                    float e00 = (key   <= row0  ) ? ex2f(S[mi][ni][0] + L0) : 0.f;
                    float e01 = (key+1 <= row0  ) ? ex2f(S[mi][ni][1] + L0) : 0.f;
                    float e10 = (key   <= row0+8) ? ex2f(S[mi][ni][2] + L1) : 0.f;
                    float e11 = (key+1 <= row0+8) ? ex2f(S[mi][ni][3] + L1) : 0.f;
                    *(float2*)&wb[(size_t)row0*SS + key]     = make_float2(e00, e01);
                    *(float2*)&wb[(size_t)(row0+8)*SS + key] = make_float2(e10, e11);
                    ap[mi][ni*2    ] = pack_h2(e00, e01);
                    ap[mi][ni*2 + 1] = pack_h2(e10, e11);
                }
            }
        }

        // PV: this warp's 16-key slice x full hd=64
        #pragma unroll
        for (int ni = 0; ni < 8; ni++) {
            uint32_t bb[2];
            ldsm2t(bb[0], bb[1],
                   sptr(&Vc[(warpN*16 + (lane & 15))*72 + ni*8]));
            mma_f16(O[0][ni], ap[0], bb);
            mma_f16(O[1][ni], ap[1], bb);
        }
    }

    // epilogue: reduce O across warpN via smem, then write fp16 apre
    __syncthreads();
    float* Osm = (float*)hsm;   // 64 x 65 fp32
    #pragma unroll 1
    for (int wn = 0; wn < 4; wn++) {
        if (warpN == wn) {
            #pragma unroll
            for (int mi = 0; mi < 2; mi++) {
                int rr = warpM*32 + mi*16 + g;
                #pragma unroll
                for (int ni = 0; ni < 8; ni++) {
                    int cc2 = ni*8 + 2*c;
                    if (wn == 0) {
                        Osm[rr*65 + cc2]       = O[mi][ni][0];
                        Osm[rr*65 + cc2 + 1]   = O[mi][ni][1];
                        Osm[(rr+8)*65 + cc2]   = O[mi][ni][2];
                        Osm[(rr+8)*65 + cc2+1] = O[mi][ni][3];
                    } else {
                        Osm[rr*65 + cc2]       += O[mi][ni][0];
                        Osm[rr*65 + cc2 + 1]   += O[mi][ni][1];
                        Osm[(rr+8)*65 + cc2]   += O[mi][ni][2];
                        Osm[(rr+8)*65 + cc2+1] += O[mi][ni][3];
                    }
                }
            }
        }
        __syncthreads();
    }

    {
        int b_ = bh >> 4, h = bh & 15;
        int row = t >> 2, cb = (t & 3) * 16;
        int s0 = q0 + row;
        uint32_t w[8];
        #pragma unroll
        for (int j = 0; j < 8; j++)
            w[j] = pack_h2(Osm[row*65 + cb + 2*j], Osm[row*65 + cb + 2*j + 1]);
        __half* dst = &g_apreh[((size_t)b_*SS + s0)*DD + h*HD + cb];
        *(uint4*)dst       = make_uint4(w[0], w[1], w[2], w[3]);
        *(uint4*)(dst + 8) = make_uint4(w[4], w[5], w[6], w[7]);
    }
}

// ---------------------------------------------------------------------------
extern "C" void kernel_launch(void* const* d_in, const int* in_sizes, int n_in,
                              void* d_out, int out_size)
{
    const float* hs = (const float*)d_in[0];
    const float* wq = (const float*)d_in[1];
    const float* bq = (const float*)d_in[2];
    const float* wk = (const float*)d_in[3];
    const float* bk = (const float*)d_in[4];
    const float* wv = (const float*)d_in[5];
    const float* bv = (const float*)d_in[6];
    const float* wc = (const float*)d_in[7];
    const float* bc = (const float*)d_in[8];

    float* out      = (float*)d_out;
    float* out_attn = out;                                   // [B,S,D]
    float* out_w    = out + (size_t)BB*SS*DD;                // [B,H,S,S]
    float* out_k    = out_w + (size_t)BB*HH*SS*SS;           // [B,H,S,hd]
    float* out_v    = out_k + (size_t)BB*HH*SS*HD;           // [B,H,S,hd]

    __half *hsh, *wt, *qh, *kh, *vh, *apreh;
    cudaGetSymbolAddress((void**)&hsh,   g_hsh);
    cudaGetSymbolAddress((void**)&wt,    g_wt);
    cudaGetSymbolAddress((void**)&qh,    g_qh);
    cudaGetSymbolAddress((void**)&kh,    g_kh);
    cudaGetSymbolAddress((void**)&vh,    g_vh);
    cudaGetSymbolAddress((void**)&apreh, g_apreh);

    cudaFuncSetAttribute(gemm_qkv,
                         cudaFuncAttributeMaxDynamicSharedMemorySize, GEMM_SMEM);
    cudaFuncSetAttribute(gemm_c,
                         cudaFuncAttributeMaxDynamicSharedMemorySize, GEMM_SMEM);
    cudaFuncSetAttribute(fattn,
                         cudaFuncAttributeMaxDynamicSharedMemorySize, FATTN_SMEM);

    conv_h<<<(MM*DD/4)/256, 256>>>(hs, hsh);
    tconv4_h<<<dim3(DD/32, DD/32, 4), 256>>>(wq, wk, wv, wc, wt);

    gemm_qkv<<<dim3(DD/128, MM/128, 3), 256, GEMM_SMEM>>>(
        hsh, wt, bq, bk, bv, out_k, out_v, qh, kh, vh);

    fattn<<<dim3(SS/64, BB*HH), 256, FATTN_SMEM>>>(kh, vh, out_w);

    gemm_c<<<dim3(DD/128, MM/128), 256, GEMM_SMEM>>>(
        apreh, wt + 3*(size_t)DD*DD, bc, out_attn);
}

// round 16
// speedup vs baseline: 1.5957x; 1.0193x over previous
#include <cuda_runtime.h>
#include <cuda_fp16.h>
#include <cstdint>
#include <math.h>

#define BB 2
#define SS 2048
#define DD 1024
#define HH 16
#define HD 64
#define MM (BB*SS)

// q pre-scale: 1/8 (attention scale) * log2(e)  -> softmax uses ex2
#define QSCL 0.18033688011112042f

// ---------------- scratch ---------------------------------------------------
__device__ __half g_hsh[MM*DD];
__device__ __half g_wt[4*DD*DD];
__device__ __half g_qh[BB*HH*SS*HD];   // pre-scaled by QSCL
__device__ __half g_kh[BB*HH*SS*HD];
__device__ __half g_vh[BB*HH*SS*HD];
__device__ __half g_apreh[MM*DD];

// ---------------- helpers ---------------------------------------------------
__device__ __forceinline__ void mma_f16(float* d, const uint32_t* a,
                                        const uint32_t* b) {
    asm volatile("mma.sync.aligned.m16n8k16.row.col.f32.f16.f16.f32 "
        "{%0,%1,%2,%3}, {%4,%5,%6,%7}, {%8,%9}, {%0,%1,%2,%3};"
        : "+f"(d[0]), "+f"(d[1]), "+f"(d[2]), "+f"(d[3])
        : "r"(a[0]), "r"(a[1]), "r"(a[2]), "r"(a[3]), "r"(b[0]), "r"(b[1]));
}
__device__ __forceinline__ void ldsm4(uint32_t* r, uint32_t sa) {
    asm volatile("ldmatrix.sync.aligned.m8n8.x4.shared.b16 {%0,%1,%2,%3}, [%4];"
        : "=r"(r[0]), "=r"(r[1]), "=r"(r[2]), "=r"(r[3]) : "r"(sa));
}
__device__ __forceinline__ void ldsm2(uint32_t& r0, uint32_t& r1, uint32_t sa) {
    asm volatile("ldmatrix.sync.aligned.m8n8.x2.shared.b16 {%0,%1}, [%2];"
        : "=r"(r0), "=r"(r1) : "r"(sa));
}
__device__ __forceinline__ void ldsm4t(uint32_t* r, uint32_t sa) {
    asm volatile("ldmatrix.sync.aligned.m8n8.x4.trans.shared.b16 {%0,%1,%2,%3}, [%4];"
        : "=r"(r[0]), "=r"(r[1]), "=r"(r[2]), "=r"(r[3]) : "r"(sa));
}
__device__ __forceinline__ void cp16(uint32_t s, const void* g) {
    asm volatile("cp.async.cg.shared.global [%0], [%1], 16;"
                 :: "r"(s), "l"(g) : "memory");
}
#define CP_COMMIT() asm volatile("cp.async.commit_group;" ::: "memory")
#define CP_WAIT(n)  asm volatile("cp.async.wait_group %0;" :: "n"(n) : "memory")
__device__ __forceinline__ uint32_t pack_h2(float a, float b) {
    __half2 h = __floats2half2_rn(a, b);
    return *(uint32_t*)&h;
}
__device__ __forceinline__ uint32_t sptr(const void* p) {
    return (uint32_t)__cvta_generic_to_shared(p);
}
__device__ __forceinline__ float ex2f(float x) {
    float r;
    asm("ex2.approx.f32 %0, %1;" : "=f"(r) : "f"(x));
    return r;
}

// ---------------------------------------------------------------------------
// conversions
// ---------------------------------------------------------------------------
__global__ __launch_bounds__(256) void conv_h(const float* __restrict__ x,
                                              __half* __restrict__ y)
{
    int i = blockIdx.x * 256 + threadIdx.x;
    float4 v = ((const float4*)x)[i];
    ((uint2*)y)[i] = make_uint2(pack_h2(v.x, v.y), pack_h2(v.z, v.w));
}

__global__ __launch_bounds__(256) void tconv4_h(const float* __restrict__ w0,
                                                const float* __restrict__ w1,
                                                const float* __restrict__ w2,
                                                const float* __restrict__ w3,
                                                __half* __restrict__ WtBase)
{
    __shared__ float tile[32][33];
    int z = blockIdx.z;
    const float* W = (z == 0) ? w0 : (z == 1) ? w1 : (z == 2) ? w2 : w3;
    __half* Wt = WtBase + (size_t)z * DD * DD;
    int tx = threadIdx.x & 31, ty = threadIdx.x >> 5;
    int k0 = blockIdx.y << 5, n0 = blockIdx.x << 5;
    #pragma unroll
    for (int i = 0; i < 4; i++)
        tile[ty + 8*i][tx] = W[(size_t)(k0 + ty + 8*i)*DD + n0 + tx];
    __syncthreads();
    #pragma unroll
    for (int i = 0; i < 4; i++)
        Wt[(size_t)(n0 + ty + 8*i)*DD + k0 + tx] = __float2half(tile[tx][ty + 8*i]);
}

// ---------------------------------------------------------------------------
// fp16 GEMM (unchanged from R15)
// ---------------------------------------------------------------------------
#define GS_T (128*40)
#define GEMM_SMEM (3*2*GS_T*2)

__device__ __forceinline__ void gemm_body(const __half* __restrict__ A,
                                          const __half* __restrict__ Wt,
                                          const float* __restrict__ bias,
                                          float* __restrict__ outf32,
                                          __half* __restrict__ outh,
                                          int split, int m0, int n0, float os)
{
    extern __shared__ __half hsm[];
    __half* As = hsm;
    __half* Bs = hsm + 3*GS_T;
    int t = threadIdx.x;
    int wid = t >> 5, lane = t & 31;
    int g = lane >> 2, c = lane & 3;
    int warpM = wid >> 2, warpN = wid & 3;

    float acc[4][4][4];
    #pragma unroll
    for (int mi = 0; mi < 4; mi++)
        #pragma unroll
        for (int ni = 0; ni < 4; ni++)
            #pragma unroll
            for (int r = 0; r < 4; r++) acc[mi][ni][r] = 0.0f;

    int lr = t >> 2, lseg = t & 3;
    const __half* Abase = A  + (size_t)(m0 + lr)*DD + lseg*8;
    const __half* Bbase = Wt + (size_t)(n0 + lr)*DD + lseg*8;
    uint32_t sA = sptr(&As[lr*40 + lseg*8]);
    uint32_t sB = sptr(&Bs[lr*40 + lseg*8]);

    int l7 = lane & 7;
    int aRow = warpM*64 + l7 + ((lane >> 3) & 1)*8;
    int aCol = (lane >> 4)*8;
    int bRow = warpN*32 + l7;
    int bCol = ((lane >> 3) & 1)*8;

    #define G_ISSUE(k0c, st) do {                                             \
        cp16(sA + (st)*(GS_T*2),             Abase + (k0c));                  \
        cp16(sA + (st)*(GS_T*2) + 64*40*2,   Abase + (size_t)64*DD + (k0c));  \
        cp16(sB + (st)*(GS_T*2),             Bbase + (k0c));                  \
        cp16(sB + (st)*(GS_T*2) + 64*40*2,   Bbase + (size_t)64*DD + (k0c));  \
        CP_COMMIT(); } while (0)

    G_ISSUE(0, 0);
    G_ISSUE(32, 1);

    for (int cc = 0; cc < 32; cc++) {
        if (cc < 31) CP_WAIT(1); else CP_WAIT(0);
        __syncthreads();
        if (cc + 2 < 32) G_ISSUE((cc+2)*32, (cc+2)%3);

        const __half* Ac = As + (cc%3)*GS_T;
        const __half* Bc = Bs + (cc%3)*GS_T;
        #pragma unroll
        for (int ks = 0; ks < 2; ks++) {
            uint32_t af[4][4], bf[4][2];
            #pragma unroll
            for (int mi = 0; mi < 4; mi++)
                ldsm4(af[mi], sptr(&Ac[(aRow + mi*16)*40 + ks*16 + aCol]));
            #pragma unroll
            for (int ni = 0; ni < 4; ni++)
                ldsm2(bf[ni][0], bf[ni][1],
                      sptr(&Bc[(bRow + ni*8)*40 + ks*16 + bCol]));
            #pragma unroll
            for (int mi = 0; mi < 4; mi++)
                #pragma unroll
                for (int ni = 0; ni < 4; ni++)
                    mma_f16(acc[mi][ni], af[mi], bf[ni]);
        }
    }

    #pragma unroll
    for (int mi = 0; mi < 4; mi++) {
        int row0 = m0 + warpM*64 + mi*16 + g;
        int b_ = row0 >> 11, s0 = row0 & 2047;
        #pragma unroll
        for (int ni = 0; ni < 4; ni++) {
            int col = n0 + warpN*32 + ni*8 + 2*c;
            float b0 = bias[col], b1 = bias[col+1];
            float2 v0 = make_float2(acc[mi][ni][0] + b0, acc[mi][ni][1] + b1);
            float2 v1 = make_float2(acc[mi][ni][2] + b0, acc[mi][ni][3] + b1);
            int h = col >> 6, ho = col & 63;
            if (outf32) {
                if (split) {
                    *(float2*)&outf32[((size_t)(b_*HH + h)*SS + s0)*HD + ho] = v0;
                    *(float2*)&outf32[((size_t)(b_*HH + h)*SS + s0 + 8)*HD + ho] = v1;
                } else {
                    *(float2*)&outf32[(size_t)row0*DD + col] = v0;
                    *(float2*)&outf32[(size_t)(row0+8)*DD + col] = v1;
                }
            }
            if (outh) {
                *(uint32_t*)&outh[((size_t)(b_*HH + h)*SS + s0)*HD + ho] =
                    pack_h2(v0.x*os, v0.y*os);
                *(uint32_t*)&outh[((size_t)(b_*HH + h)*SS + s0 + 8)*HD + ho] =
                    pack_h2(v1.x*os, v1.y*os);
            }
        }
    }
}

__global__ __launch_bounds__(256, 2) void gemm_qkv(const __half* __restrict__ A,
                                                   const __half* __restrict__ wt,
                                                   const float* __restrict__ bq,
                                                   const float* __restrict__ bk,
                                                   const float* __restrict__ bv,
                                                   float* __restrict__ out_k,
                                                   float* __restrict__ out_v,
                                                   __half* __restrict__ qh,
                                                   __half* __restrict__ kh,
                                                   __half* __restrict__ vh)
{
    int z = blockIdx.z;
    const __half* Wt = wt + (size_t)z * DD * DD;
    const float* bias = (z == 0) ? bq : (z == 1) ? bk : bv;
    float* of  = (z == 0) ? nullptr : (z == 1) ? out_k : out_v;
    __half* oh = (z == 0) ? qh : (z == 1) ? kh : vh;
    float os   = (z == 0) ? QSCL : 1.0f;
    gemm_body(A, Wt, bias, of, oh, 1, blockIdx.y << 7, blockIdx.x << 7, os);
}

__global__ __launch_bounds__(256, 2) void gemm_c(const __half* __restrict__ A,
                                                 const __half* __restrict__ Wt,
                                                 const float* __restrict__ bias,
                                                 float* __restrict__ outf32)
{
    gemm_body(A, Wt, bias, outf32, nullptr, 0, blockIdx.y << 7, blockIdx.x << 7, 1.0f);
}

// ---------------------------------------------------------------------------
// Fused attention. Warp layout 4(M) x 2(N): 16 q-rows per warpM, 32-key
// slice per warpN. O[8][4]=32 regs -> 3 CTAs/SM. K via ldmatrix.x4,
// V via ldmatrix.x4.trans. Two phases as R15, diag-specialized.
// ---------------------------------------------------------------------------
#define AT_T (64*72)
#define FATTN_SMEM (5*AT_T*2)

__global__ __launch_bounds__(256, 3) void fattn(const __half* __restrict__ kin,
                                                const __half* __restrict__ vin,
                                                float* __restrict__ attnw)
{
    extern __shared__ __half hsm[];
    __half* Qs = hsm;                      // 64x72

    int bh = blockIdx.y;
    int qtile = gridDim.x - 1 - blockIdx.x;   // heavy tiles first
    int q0 = qtile << 6;
    int t = threadIdx.x;
    int wid = t >> 5, lane = t & 31;
    int g = lane >> 2, c = lane & 3;
    int warpM = wid >> 1;                  // 0..3 (16 q-rows each)
    int warpN = wid & 1;                   // 0..1 (32-key slice each)

    const __half* qb = g_qh + (size_t)bh * SS * HD;
    const __half* kb = kin  + (size_t)bh * SS * HD;
    const __half* vb = vin  + (size_t)bh * SS * HD;
    float*        wb = attnw + (size_t)bh * SS * SS;

    // zero-fill upper triangle strip (overlaps with compute)
    {
        float4 z = make_float4(0.f, 0.f, 0.f, 0.f);
        int zr = q0 + (t >> 2);
        for (int col = q0 + 64 + (t & 3)*4; col < SS; col += 16)
            *(float4*)&wb[(size_t)zr*SS + col] = z;
    }

    int lr = t >> 3, lseg = t & 7;
    int l7 = lane & 7;
    // A (Q / rows) ldsm4 lane addressing: 16 rows x k16
    int aRow = warpM*16 + l7 + ((lane >> 3) & 1)*8;
    int aCol = (lane >> 4)*8;
    // B (K) ldsm4 lane addressing: 2 n8 groups x k16 per load
    int bR = ((lane >> 4) & 1)*8 + l7;     // + warpN*32 + pair*16
    int bC = ((lane >> 3) & 1)*8;          // + ks*16
    // V ldsm4t lane addressing: 16 k-rows x 2 hd groups
    int vR = lane & 15;                     // + warpN*32 + ck*16
    int vC = ((lane >> 4) & 1)*8;          // + nib*8

    // Q load
    uint32_t sQ = sptr(&Qs[lr*72 + lseg*8]);
    cp16(sQ,           &qb[(size_t)(q0 + lr)*HD + lseg*8]);
    cp16(sQ + 32*72*2, &qb[(size_t)(q0 + lr + 32)*HD + lseg*8]);
    CP_COMMIT();

    int nkb = qtile + 1;
    int nkb128 = (nkb + 1) >> 1;

    // phase-1 stage bases (128 rows each)
    uint32_t sK1 = sptr(&hsm[AT_T + lr*72 + lseg*8]);
    #define K128_ISSUE(kpos0, st) do {                                        \
        _Pragma("unroll")                                                     \
        for (int i = 0; i < 4; i++)                                           \
            cp16(sK1 + (st)*(2*AT_T*2) + i*(32*72*2),                         \
                 &kb[(size_t)((kpos0) + lr + 32*i)*HD + lseg*8]);             \
        CP_COMMIT(); } while (0)

    K128_ISSUE(0, 0);
    CP_WAIT(0);
    __syncthreads();

    // hoist Q fragments for phase 1 (16 regs)
    uint32_t qf[4][4];
    #pragma unroll
    for (int ks = 0; ks < 4; ks++)
        ldsm4(qf[ks], sptr(&Qs[aRow*72 + ks*16 + aCol]));

    if (nkb128 > 1) K128_ISSUE(128, 1);

    float psum[2] = {0.f, 0.f};

    for (int j = 0; j < nkb128; j++) {
        if (j > 0) {
            CP_WAIT(0);
            __syncthreads();
            if (j + 1 < nkb128) K128_ISSUE((j+1)*128, (j+1) & 1);
        }
        const __half* Kst = hsm + AT_T + (j & 1)*(2*AT_T);

        #pragma unroll
        for (int sb = 0; sb < 2; sb++) {
            int kb2 = j*2 + sb;
            if (kb2 >= nkb) break;
            const __half* Kc = Kst + sb*(64*72);
            int kpos0 = kb2 << 6;
            bool diag = (kb2 == nkb - 1);

            float S[4][4];
            #pragma unroll
            for (int ni = 0; ni < 4; ni++)
                #pragma unroll
                for (int r = 0; r < 4; r++) S[ni][r] = 0.0f;

            #pragma unroll
            for (int ks = 0; ks < 4; ks++) {
                #pragma unroll
                for (int pair = 0; pair < 2; pair++) {
                    uint32_t bf4[4];
                    ldsm4(bf4, sptr(&Kc[(warpN*32 + pair*16 + bR)*72
                                        + ks*16 + bC]));
                    mma_f16(S[pair*2    ], qf[ks], bf4);
                    mma_f16(S[pair*2 + 1], qf[ks], bf4 + 2);
                }
            }

            if (!diag) {
                #pragma unroll
                for (int ni = 0; ni < 4; ni++) {
                    psum[0] += ex2f(S[ni][0]) + ex2f(S[ni][1]);
                    psum[1] += ex2f(S[ni][2]) + ex2f(S[ni][3]);
                }
            } else {
                int row0 = q0 + warpM*16 + g;
                #pragma unroll
                for (int ni = 0; ni < 4; ni++) {
                    int key = kpos0 + warpN*32 + ni*8 + 2*c;
                    psum[0] += ((key   <= row0  ) ? ex2f(S[ni][0]) : 0.f)
                             + ((key+1 <= row0  ) ? ex2f(S[ni][1]) : 0.f);
                    psum[1] += ((key   <= row0+8) ? ex2f(S[ni][2]) : 0.f)
                             + ((key+1 <= row0+8) ? ex2f(S[ni][3]) : 0.f);
                }
            }
        }
    }
    __syncthreads();

    // reduce -> log2(1/l)
    float* red = (float*)(hsm + AT_T);
    #pragma unroll
    for (int hh = 0; hh < 2; hh++) {
        float v = psum[hh];
        v += __shfl_xor_sync(0xFFFFFFFF, v, 1);
        v += __shfl_xor_sync(0xFFFFFFFF, v, 2);
        psum[hh] = v;
    }
    if (c == 0) {
        #pragma unroll
        for (int hh = 0; hh < 2; hh++) {
            int lrow = warpM*16 + g + hh*8;
            red[lrow*2 + warpN] = psum[hh];
        }
    }
    __syncthreads();
    if (t < 64) {
        float l = red[t*2] + red[t*2 + 1];
        red[128 + t] = 1.0f / l;
    }
    __syncthreads();

    float L2i[2];
    {
        int lrow = warpM*16 + g;
        L2i[0] = __log2f(red[128 + lrow]);
        L2i[1] = __log2f(red[128 + lrow + 8]);
    }
    __syncthreads();   // before phase-2 cp.async overwrites red region

    // ---------------- phase 2: weights + PV ----------------
    uint32_t sK2 = sptr(&hsm[AT_T   + lr*72 + lseg*8]);
    uint32_t sV2 = sptr(&hsm[3*AT_T + lr*72 + lseg*8]);
    #define KV_ISSUE(kpos0, st) do {                                          \
        cp16(sK2 + (st)*(AT_T*2),           &kb[(size_t)((kpos0)+lr)*HD + lseg*8]);    \
        cp16(sK2 + (st)*(AT_T*2) + 32*72*2, &kb[(size_t)((kpos0)+lr+32)*HD + lseg*8]); \
        cp16(sV2 + (st)*(AT_T*2),           &vb[(size_t)((kpos0)+lr)*HD + lseg*8]);    \
        cp16(sV2 + (st)*(AT_T*2) + 32*72*2, &vb[(size_t)((kpos0)+lr+32)*HD + lseg*8]); \
        CP_COMMIT(); } while (0)

    float O[8][4];
    #pragma unroll
    for (int ni = 0; ni < 8; ni++)
        #pragma unroll
        for (int r = 0; r < 4; r++) O[ni][r] = 0.0f;

    KV_ISSUE(0, 0);

    for (int kb2 = 0; kb2 < nkb; kb2++) {
        CP_WAIT(0);
        __syncthreads();
        if (kb2 + 1 < nkb) KV_ISSUE((kb2+1) << 6, (kb2+1) & 1);

        const __half* Kc = hsm + AT_T   + (kb2 & 1)*AT_T;
        const __half* Vc = hsm + 3*AT_T + (kb2 & 1)*AT_T;
        int kpos0 = kb2 << 6;
        bool diag = (kb2 == nkb - 1);

        float S[4][4];
        #pragma unroll
        for (int ni = 0; ni < 4; ni++)
            #pragma unroll
            for (int r = 0; r < 4; r++) S[ni][r] = 0.0f;

        #pragma unroll
        for (int ks = 0; ks < 4; ks++) {
            uint32_t af[4];
            ldsm4(af, sptr(&Qs[aRow*72 + ks*16 + aCol]));
            #pragma unroll
            for (int pair = 0; pair < 2; pair++) {
                uint32_t bf4[4];
                ldsm4(bf4, sptr(&Kc[(warpN*32 + pair*16 + bR)*72
                                    + ks*16 + bC]));
                mma_f16(S[pair*2    ], af, bf4);
                mma_f16(S[pair*2 + 1], af, bf4 + 2);
            }
        }

        // normalized weights; store attnw; pack PV A-fragments
        uint32_t ap[2][4];
        int lrow0 = warpM*16 + g;
        int row0 = q0 + lrow0;
        float L0 = L2i[0], L1 = L2i[1];
        if (!diag) {
            #pragma unroll
            for (int ni = 0; ni < 4; ni++) {
                int key = kpos0 + warpN*32 + ni*8 + 2*c;
                float e00 = ex2f(S[ni][0] + L0);
                float e01 = ex2f(S[ni][1] + L0);
                float e10 = ex2f(S[ni][2] + L1);
                float e11 = ex2f(S[ni][3] + L1);
                *(float2*)&wb[(size_t)row0*SS + key]     = make_float2(e00, e01);
                *(float2*)&wb[(size_t)(row0+8)*SS + key] = make_float2(e10, e11);
                ap[ni>>1][(ni&1)*2    ] = pack_h2(e00, e01);
                ap[ni>>1][(ni&1)*2 + 1] = pack_h2(e10, e11);
            }
        } else {
            #pragma unroll
            for (int ni = 0; ni < 4; ni++) {
                int key = kpos0 + warpN*32 + ni*8 + 2*c;
                float e00 = (key   <= row0  ) ? ex2f(S[ni][0] + L0) : 0.f;
                float e01 = (key+1 <= row0  ) ? ex2f(S[ni][1] + L0) : 0.f;
                float e10 = (key   <= row0+8) ? ex2f(S[ni][2] + L1) : 0.f;
                float e11 = (key+1 <= row0+8) ? ex2f(S[ni][3] + L1) : 0.f;
                *(float2*)&wb[(size_t)row0*SS + key]     = make_float2(e00, e01);
                *(float2*)&wb[(size_t)(row0+8)*SS + key] = make_float2(e10, e11);
                ap[ni>>1][(ni&1)*2    ] = pack_h2(e00, e01);
                ap[ni>>1][(ni&1)*2 + 1] = pack_h2(e10, e11);
            }
        }

        // PV: 2 key-chunks (k16) x 8 hd-cols (2 per ldsm4t)
        #pragma unroll
        for (int ck = 0; ck < 2; ck++) {
            #pragma unroll
            for (int nib = 0; nib < 8; nib += 2) {
                uint32_t bb4[4];
                ldsm4t(bb4, sptr(&Vc[(warpN*32 + ck*16 + vR)*72
                                     + nib*8 + vC]));
                mma_f16(O[nib    ], ap[ck], bb4);
                mma_f16(O[nib + 1], ap[ck], bb4 + 2);
            }
        }
    }

    // epilogue: reduce O across 2 warpN groups via smem, write fp16 apre
    __syncthreads();
    float* Osm = (float*)hsm;   // 64 x 65 fp32
    #pragma unroll 1
    for (int wn = 0; wn < 2; wn++) {
        if (warpN == wn) {
            int rr = warpM*16 + g;
            #pragma unroll
            for (int ni = 0; ni < 8; ni++) {
                int cc2 = ni*8 + 2*c;
                if (wn == 0) {
                    Osm[rr*65 + cc2]       = O[ni][0];
                    Osm[rr*65 + cc2 + 1]   = O[ni][1];
                    Osm[(rr+8)*65 + cc2]   = O[ni][2];
                    Osm[(rr+8)*65 + cc2+1] = O[ni][3];
                } else {
                    Osm[rr*65 + cc2]       += O[ni][0];
                    Osm[rr*65 + cc2 + 1]   += O[ni][1];
                    Osm[(rr+8)*65 + cc2]   += O[ni][2];
                    Osm[(rr+8)*65 + cc2+1] += O[ni][3];
                }
            }
        }
        __syncthreads();
    }

    {
        // normalize by inv (O currently unnormalized? no - weights already
        // normalized via L2i in exp) -> direct write
        int b_ = bh >> 4, h = bh & 15;
        int row = t >> 2, cb = (t & 3) * 16;
        int s0 = q0 + row;
        uint32_t w[8];
        #pragma unroll
        for (int j = 0; j < 8; j++)
            w[j] = pack_h2(Osm[row*65 + cb + 2*j], Osm[row*65 + cb + 2*j + 1]);
        __half* dst = &g_apreh[((size_t)b_*SS + s0)*DD + h*HD + cb];
        *(uint4*)dst       = make_uint4(w[0], w[1], w[2], w[3]);
        *(uint4*)(dst + 8) = make_uint4(w[4], w[5], w[6], w[7]);
    }
}

// ---------------------------------------------------------------------------
extern "C" void kernel_launch(void* const* d_in, const int* in_sizes, int n_in,
                              void* d_out, int out_size)
{
    const float* hs = (const float*)d_in[0];
    const float* wq = (const float*)d_in[1];
    const float* bq = (const float*)d_in[2];
    const float* wk = (const float*)d_in[3];
    const float* bk = (const float*)d_in[4];
    const float* wv = (const float*)d_in[5];
    const float* bv = (const float*)d_in[6];
    const float* wc = (const float*)d_in[7];
    const float* bc = (const float*)d_in[8];

    float* out      = (float*)d_out;
    float* out_attn = out;                                   // [B,S,D]
    float* out_w    = out + (size_t)BB*SS*DD;                // [B,H,S,S]
    float* out_k    = out_w + (size_t)BB*HH*SS*SS;           // [B,H,S,hd]
    float* out_v    = out_k + (size_t)BB*HH*SS*HD;           // [B,H,S,hd]

    __half *hsh, *wt, *qh, *kh, *vh, *apreh;
    cudaGetSymbolAddress((void**)&hsh,   g_hsh);
    cudaGetSymbolAddress((void**)&wt,    g_wt);
    cudaGetSymbolAddress((void**)&qh,    g_qh);
    cudaGetSymbolAddress((void**)&kh,    g_kh);
    cudaGetSymbolAddress((void**)&vh,    g_vh);
    cudaGetSymbolAddress((void**)&apreh, g_apreh);

    cudaFuncSetAttribute(gemm_qkv,
                         cudaFuncAttributeMaxDynamicSharedMemorySize, GEMM_SMEM);
    cudaFuncSetAttribute(gemm_c,
                         cudaFuncAttributeMaxDynamicSharedMemorySize, GEMM_SMEM);
    cudaFuncSetAttribute(fattn,
                         cudaFuncAttributeMaxDynamicSharedMemorySize, FATTN_SMEM);

    conv_h<<<(MM*DD/4)/256, 256>>>(hs, hsh);
    tconv4_h<<<dim3(DD/32, DD/32, 4), 256>>>(wq, wk, wv, wc, wt);

    gemm_qkv<<<dim3(DD/128, MM/128, 3), 256, GEMM_SMEM>>>(
        hsh, wt, bq, bk, bv, out_k, out_v, qh, kh, vh);

    fattn<<<dim3(SS/64, BB*HH), 256, FATTN_SMEM>>>(kh, vh, out_w);

    gemm_c<<<dim3(DD/128, MM/128), 256, GEMM_SMEM>>>(
        apreh, wt + 3*(size_t)DD*DD, bc, out_attn);
}

// round 17
// speedup vs baseline: 1.6502x; 1.0342x over previous
#include <cuda_runtime.h>
#include <cuda_fp16.h>
#include <cstdint>
#include <math.h>

#define BB 2
#define SS 2048
#define DD 1024
#define HH 16
#define HD 64
#define MM (BB*SS)

#define QSCL 0.18033688011112042f

__device__ __half g_hsh[MM*DD];
__device__ __half g_wt[4*DD*DD];
__device__ __half g_qh[BB*HH*SS*HD];
__device__ __half g_kh[BB*HH*SS*HD];
__device__ __half g_vh[BB*HH*SS*HD];
__device__ __half g_apreh[MM*DD];

__device__ __forceinline__ void mma_f16(float* d, const uint32_t* a,
                                        const uint32_t* b) {
    asm volatile("mma.sync.aligned.m16n8k16.row.col.f32.f16.f16.f32 "
        "{%0,%1,%2,%3}, {%4,%5,%6,%7}, {%8,%9}, {%0,%1,%2,%3};"
        : "+f"(d[0]), "+f"(d[1]), "+f"(d[2]), "+f"(d[3])
        : "r"(a[0]), "r"(a[1]), "r"(a[2]), "r"(a[3]), "r"(b[0]), "r"(b[1]));
}
__device__ __forceinline__ void ldsm4(uint32_t* r, uint32_t sa) {
    asm volatile("ldmatrix.sync.aligned.m8n8.x4.shared.b16 {%0,%1,%2,%3}, [%4];"
        : "=r"(r[0]), "=r"(r[1]), "=r"(r[2]), "=r"(r[3]) : "r"(sa));
}
__device__ __forceinline__ void ldsm2(uint32_t& r0, uint32_t& r1, uint32_t sa) {
    asm volatile("ldmatrix.sync.aligned.m8n8.x2.shared.b16 {%0,%1}, [%2];"
        : "=r"(r0), "=r"(r1) : "r"(sa));
}
__device__ __forceinline__ void ldsm4t(uint32_t* r, uint32_t sa) {
    asm volatile("ldmatrix.sync.aligned.m8n8.x4.trans.shared.b16 {%0,%1,%2,%3}, [%4];"
        : "=r"(r[0]), "=r"(r[1]), "=r"(r[2]), "=r"(r[3]) : "r"(sa));
}
__device__ __forceinline__ void cp16(uint32_t s, const void* g) {
    asm volatile("cp.async.cg.shared.global [%0], [%1], 16;"
                 :: "r"(s), "l"(g) : "memory");
}
#define CP_COMMIT() asm volatile("cp.async.commit_group;" ::: "memory")
#define CP_WAIT(n)  asm volatile("cp.async.wait_group %0;" :: "n"(n) : "memory")
__device__ __forceinline__ uint32_t pack_h2(float a, float b) {
    __half2 h = __floats2half2_rn(a, b);
    return *(uint32_t*)&h;
}
__device__ __forceinline__ uint32_t sptr(const void* p) {
    return (uint32_t)__cvta_generic_to_shared(p);
}
__device__ __forceinline__ float ex2f(float x) {
    float r;
    asm("ex2.approx.f32 %0, %1;" : "=f"(r) : "f"(x));
    return r;
}

__global__ __launch_bounds__(256) void conv_h(const float* __restrict__ x,
                                              __half* __restrict__ y)
{
    int i = blockIdx.x * 256 + threadIdx.x;
    float4 v = ((const float4*)x)[i];
    ((uint2*)y)[i] = make_uint2(pack_h2(v.x, v.y), pack_h2(v.z, v.w));
}

__global__ __launch_bounds__(256) void tconv4_h(const float* __restrict__ w0,
                                                const float* __restrict__ w1,
                                                const float* __restrict__ w2,
                                                const float* __restrict__ w3,
                                                __half* __restrict__ WtBase)
{
    __shared__ float tile[32][33];
    int z = blockIdx.z;
    const float* W = (z == 0) ? w0 : (z == 1) ? w1 : (z == 2) ? w2 : w3;
    __half* Wt = WtBase + (size_t)z * DD * DD;
    int tx = threadIdx.x & 31, ty = threadIdx.x >> 5;
    int k0 = blockIdx.y << 5, n0 = blockIdx.x << 5;
    #pragma unroll
    for (int i = 0; i < 4; i++)
        tile[ty + 8*i][tx] = W[(size_t)(k0 + ty + 8*i)*DD + n0 + tx];
    __syncthreads();
    #pragma unroll
    for (int i = 0; i < 4; i++)
        Wt[(size_t)(n0 + ty + 8*i)*DD + k0 + tx] = __float2half(tile[tx][ty + 8*i]);
}

#define GS_T (128*72)
#define GEMM_SMEM (3*2*GS_T*2)

__device__ __forceinline__ void gemm_body(const __half* __restrict__ A,
                                          const __half* __restrict__ Wt,
                                          const float* __restrict__ bias,
                                          float* __restrict__ outf32,
                                          __half* __restrict__ outh,
                                          int split, int m0, int n0, float os)
{
    extern __shared__ __half hsm[];
    __half* As = hsm;
    __half* Bs = hsm + 3*GS_T;
    int t = threadIdx.x;
    int wid = t >> 5, lane = t & 31;
    int g = lane >> 2, c = lane & 3;
    int warpM = wid >> 2, warpN = wid & 3;

    float acc[4][4][4];
    #pragma unroll
    for (int mi = 0; mi < 4; mi++)
        #pragma unroll
        for (int ni = 0; ni < 4; ni++)
            #pragma unroll
            for (int r = 0; r < 4; r++) acc[mi][ni][r] = 0.0f;

    int lr = t >> 3, lseg = t & 7;
    const __half* Abase = A  + (size_t)(m0 + lr)*DD + lseg*8;
    const __half* Bbase = Wt + (size_t)(n0 + lr)*DD + lseg*8;
    uint32_t sA = sptr(&As[lr*72 + lseg*8]);
    uint32_t sB = sptr(&Bs[lr*72 + lseg*8]);

    int l7 = lane & 7;
    int aRow = warpM*64 + l7 + ((lane >> 3) & 1)*8;
    int aCol = (lane >> 4)*8;
    int bRow = warpN*32 + l7;
    int bCol = ((lane >> 3) & 1)*8;

    #define G_ISSUE(k0c, st) do {                                             \
        _Pragma("unroll")                                                     \
        for (int i = 0; i < 4; i++) {                                         \
            cp16(sA + (st)*(GS_T*2) + i*(32*72*2),                            \
                 Abase + (size_t)(32*i)*DD + (k0c));                          \
            cp16(sB + (st)*(GS_T*2) + i*(32*72*2),                            \
                 Bbase + (size_t)(32*i)*DD + (k0c));                          \
        }                                                                     \
        CP_COMMIT(); } while (0)

    G_ISSUE(0, 0);
    G_ISSUE(64, 1);

    for (int cc = 0; cc < 16; cc++) {
        if (cc < 15) CP_WAIT(1); else CP_WAIT(0);
        __syncthreads();
        if (cc + 2 < 16) G_ISSUE((cc+2)*64, (cc+2)%3);

        const __half* Ac = As + (cc%3)*GS_T;
        const __half* Bc = Bs + (cc%3)*GS_T;
        #pragma unroll
        for (int ks = 0; ks < 4; ks++) {
            uint32_t af[4][4], bf[4][2];
            #pragma unroll
            for (int mi = 0; mi < 4; mi++)
                ldsm4(af[mi], sptr(&Ac[(aRow + mi*16)*72 + ks*16 + aCol]));
            #pragma unroll
            for (int ni = 0; ni < 4; ni++)
                ldsm2(bf[ni][0], bf[ni][1],
                      sptr(&Bc[(bRow + ni*8)*72 + ks*16 + bCol]));
            #pragma unroll
            for (int mi = 0; mi < 4; mi++)
                #pragma unroll
                for (int ni = 0; ni < 4; ni++)
                    mma_f16(acc[mi][ni], af[mi], bf[ni]);
        }
    }

    #pragma unroll
    for (int mi = 0; mi < 4; mi++) {
        int row0 = m0 + warpM*64 + mi*16 + g;
        int b_ = row0 >> 11, s0 = row0 & 2047;
        #pragma unroll
        for (int ni = 0; ni < 4; ni++) {
            int col = n0 + warpN*32 + ni*8 + 2*c;
            float b0 = bias[col], b1 = bias[col+1];
            float2 v0 = make_float2(acc[mi][ni][0] + b0, acc[mi][ni][1] + b1);
            float2 v1 = make_float2(acc[mi][ni][2] + b0, acc[mi][ni][3] + b1);
            int h = col >> 6, ho = col & 63;
            if (outf32) {
                if (split) {
                    *(float2*)&outf32[((size_t)(b_*HH + h)*SS + s0)*HD + ho] = v0;
                    *(float2*)&outf32[((size_t)(b_*HH + h)*SS + s0 + 8)*HD + ho] = v1;
                } else {
                    *(float2*)&outf32[(size_t)row0*DD + col] = v0;
                    *(float2*)&outf32[(size_t)(row0+8)*DD + col] = v1;
                }
            }
            if (outh) {
                *(uint32_t*)&outh[((size_t)(b_*HH + h)*SS + s0)*HD + ho] =
                    pack_h2(v0.x*os, v0.y*os);
                *(uint32_t*)&outh[((size_t)(b_*HH + h)*SS + s0 + 8)*HD + ho] =
                    pack_h2(v1.x*os, v1.y*os);
            }
        }
    }
}

__global__ __launch_bounds__(256, 2) void gemm_qkv(const __half* __restrict__ A,
                                                   const __half* __restrict__ wt,
                                                   const float* __restrict__ bq,
                                                   const float* __restrict__ bk,
                                                   const float* __restrict__ bv,
                                                   float* __restrict__ out_k,
                                                   float* __restrict__ out_v,
                                                   __half* __restrict__ qh,
                                                   __half* __restrict__ kh,
                                                   __half* __restrict__ vh)
{
    int z = blockIdx.z;
    const __half* Wt = wt + (size_t)z * DD * DD;
    const float* bias = (z == 0) ? bq : (z == 1) ? bk : bv;
    float* of  = (z == 0) ? nullptr : (z == 1) ? out_k : out_v;
    __half* oh = (z == 0) ? qh : (z == 1) ? kh : vh;
    float os   = (z == 0) ? QSCL : 1.0f;
    gemm_body(A, Wt, bias, of, oh, 1, blockIdx.y << 7, blockIdx.x << 7, os);
}

__global__ __launch_bounds__(256, 2) void gemm_c(const __half* __restrict__ A,
                                                 const __half* __restrict__ Wt,
                                                 const float* __restrict__ bias,
                                                 float* __restrict__ outf32)
{
    gemm_body(A, Wt, bias, outf32, nullptr, 0, blockIdx.y << 7, blockIdx.x << 7, 1.0f);
}

#define AT_T (64*72)
#define FATTN_SMEM (9*AT_T*2)

__global__ __launch_bounds__(256, 2) void fattn(const __half* __restrict__ kin,
                                                const __half* __restrict__ vin,
                                                float* __restrict__ attnw)
{
    extern __shared__ __half hsm[];
    __half* Qs = hsm;

    int bh = blockIdx.y;
    int qtile = gridDim.x - 1 - blockIdx.x;
    int q0 = qtile << 6;
    int t = threadIdx.x;
    int wid = t >> 5, lane = t & 31;
    int g = lane >> 2, c = lane & 3;
    int warpM = wid >> 1;
    int warpN = wid & 1;

    const __half* qb = g_qh + (size_t)bh * SS * HD;
    const __half* kb = kin  + (size_t)bh * SS * HD;
    const __half* vb = vin  + (size_t)bh * SS * HD;
    float*        wb = attnw + (size_t)bh * SS * SS;

    {
        float4 z = make_float4(0.f, 0.f, 0.f, 0.f);
        int zr = q0 + (t >> 2);
        for (int col = q0 + 64 + (t & 3)*4; col < SS; col += 16)
            *(float4*)&wb[(size_t)zr*SS + col] = z;
    }

    int lr = t >> 3, lseg = t & 7;
    int l7 = lane & 7;
    int aRow = warpM*16 + l7 + ((lane >> 3) & 1)*8;
    int aCol = (lane >> 4)*8;
    int bR = ((lane >> 4) & 1)*8 + l7;
    int bC = ((lane >> 3) & 1)*8;
    int vR = lane & 15;
    int vC = ((lane >> 4) & 1)*8;

    uint32_t sQ = sptr(&Qs[lr*72 + lseg*8]);
    cp16(sQ,           &qb[(size_t)(q0 + lr)*HD + lseg*8]);
    cp16(sQ + 32*72*2, &qb[(size_t)(q0 + lr + 32)*HD + lseg*8]);
    CP_COMMIT();

    int nkb = qtile + 1;
    int nkb128 = (nkb + 1) >> 1;

    uint32_t sK1 = sptr(&hsm[AT_T + lr*72 + lseg*8]);
    #define K128_ISSUE(kpos0, st) do {                                        \
        _Pragma("unroll")                                                     \
        for (int i = 0; i < 4; i++)                                           \
            cp16(sK1 + (st)*(2*AT_T*2) + i*(32*72*2),                         \
                 &kb[(size_t)((kpos0) + lr + 32*i)*HD + lseg*8]);             \
        CP_COMMIT(); } while (0)

    K128_ISSUE(0, 0);
    CP_WAIT(0);
    __syncthreads();

    uint32_t qf[4][4];
    #pragma unroll
    for (int ks = 0; ks < 4; ks++)
        ldsm4(qf[ks], sptr(&Qs[aRow*72 + ks*16 + aCol]));

    if (nkb128 > 1) K128_ISSUE(128, 1);

    float psum[2] = {0.f, 0.f};

    for (int j = 0; j < nkb128; j++) {
        if (j > 0) {
            CP_WAIT(0);
            __syncthreads();
            if (j + 1 < nkb128) K128_ISSUE((j+1)*128, (j+1) & 1);
        }
        const __half* Kst = hsm + AT_T + (j & 1)*(2*AT_T);

        #pragma unroll
        for (int sb = 0; sb < 2; sb++) {
            int kb2 = j*2 + sb;
            if (kb2 >= nkb) break;
            const __half* Kc = Kst + sb*(64*72);
            int kpos0 = kb2 << 6;
            bool diag = (kb2 == nkb - 1);

            float S[4][4];
            #pragma unroll
            for (int ni = 0; ni < 4; ni++)
                #pragma unroll
                for (int r = 0; r < 4; r++) S[ni][r] = 0.0f;

            #pragma unroll
            for (int ks = 0; ks < 4; ks++) {
                #pragma unroll
                for (int pair = 0; pair < 2; pair++) {
                    uint32_t bf4[4];
                    ldsm4(bf4, sptr(&Kc[(warpN*32 + pair*16 + bR)*72
                                        + ks*16 + bC]));
                    mma_f16(S[pair*2    ], qf[ks], bf4);
                    mma_f16(S[pair*2 + 1], qf[ks], bf4 + 2);
                }
            }

            if (!diag) {
                #pragma unroll
                for (int ni = 0; ni < 4; ni++) {
                    psum[0] += ex2f(S[ni][0]) + ex2f(S[ni][1]);
                    psum[1] += ex2f(S[ni][2]) + ex2f(S[ni][3]);
                }
            } else {
                int row0 = q0 + warpM*16 + g;
                #pragma unroll
                for (int ni = 0; ni < 4; ni++) {
                    int key = kpos0 + warpN*32 + ni*8 + 2*c;
                    psum[0] += ((key   <= row0  ) ? ex2f(S[ni][0]) : 0.f)
                             + ((key+1 <= row0  ) ? ex2f(S[ni][1]) : 0.f);
                    psum[1] += ((key   <= row0+8) ? ex2f(S[ni][2]) : 0.f)
                             + ((key+1 <= row0+8) ? ex2f(S[ni][3]) : 0.f);
                }
            }
        }
    }
    __syncthreads();

    float* red = (float*)(hsm + AT_T);
    #pragma unroll
    for (int hh = 0; hh < 2; hh++) {
        float v = psum[hh];
        v += __shfl_xor_sync(0xFFFFFFFF, v, 1);
        v += __shfl_xor_sync(0xFFFFFFFF, v, 2);
        psum[hh] = v;
    }
    if (c == 0) {
        #pragma unroll
        for (int hh = 0; hh < 2; hh++) {
            int lrow = warpM*16 + g + hh*8;
            red[lrow*2 + warpN] = psum[hh];
        }
    }
    __syncthreads();
    if (t < 64) {
        float l = red[t*2] + red[t*2 + 1];
        red[128 + t] = 1.0f / l;
    }
    __syncthreads();

    float L2i[2];
    {
        int lrow = warpM*16 + g;
        L2i[0] = __log2f(red[128 + lrow]);
        L2i[1] = __log2f(red[128 + lrow + 8]);
    }
    __syncthreads();

    uint32_t sK2 = sptr(&hsm[AT_T   + lr*72 + lseg*8]);
    uint32_t sV2 = sptr(&hsm[5*AT_T + lr*72 + lseg*8]);
    #define KV128_ISSUE(kpos0, st) do {                                       \
        _Pragma("unroll")                                                     \
        for (int i = 0; i < 4; i++) {                                         \
            cp16(sK2 + (st)*(2*AT_T*2) + i*(32*72*2),                         \
                 &kb[(size_t)((kpos0) + lr + 32*i)*HD + lseg*8]);             \
            cp16(sV2 + (st)*(2*AT_T*2) + i*(32*72*2),                         \
                 &vb[(size_t)((kpos0) + lr + 32*i)*HD + lseg*8]);             \
        }                                                                     \
        CP_COMMIT(); } while (0)

    float O[8][4];
    #pragma unroll
    for (int ni = 0; ni < 8; ni++)
        #pragma unroll
        for (int r = 0; r < 4; r++) O[ni][r] = 0.0f;

    KV128_ISSUE(0, 0);

    for (int j = 0; j < nkb128; j++) {
        CP_WAIT(0);
        __syncthreads();
        if (j + 1 < nkb128) KV128_ISSUE((j+1)*128, (j+1) & 1);

        const __half* Kst = hsm + AT_T   + (j & 1)*(2*AT_T);
        const __half* Vst = hsm + 5*AT_T + (j & 1)*(2*AT_T);

        #pragma unroll
        for (int sb = 0; sb < 2; sb++) {
            int kb2 = j*2 + sb;
            if (kb2 >= nkb) break;
            const __half* Kc = Kst + sb*(64*72);
            const __half* Vc = Vst + sb*(64*72);
            int kpos0 = kb2 << 6;
            bool diag = (kb2 == nkb - 1);

            float S[4][4];
            #pragma unroll
            for (int ni = 0; ni < 4; ni++)
                #pragma unroll
                for (int r = 0; r < 4; r++) S[ni][r] = 0.0f;

            #pragma unroll
            for (int ks = 0; ks < 4; ks++) {
                #pragma unroll
                for (int pair = 0; pair < 2; pair++) {
                    uint32_t bf4[4];
                    ldsm4(bf4, sptr(&Kc[(warpN*32 + pair*16 + bR)*72
                                        + ks*16 + bC]));
                    mma_f16(S[pair*2    ], qf[ks], bf4);
                    mma_f16(S[pair*2 + 1], qf[ks], bf4 + 2);
                }
            }

            uint32_t ap[2][4];
            int row0 = q0 + warpM*16 + g;
            float L0 = L2i[0], L1 = L2i[1];
            if (!diag) {
                #pragma unroll
                for (int ni = 0; ni < 4; ni++) {
                    int key = kpos0 + warpN*32 + ni*8 + 2*c;
                    float e00 = ex2f(S[ni][0] + L0);
                    float e01 = ex2f(S[ni][1] + L0);
                    float e10 = ex2f(S[ni][2] + L1);
                    float e11 = ex2f(S[ni][3] + L1);
                    *(float2*)&wb[(size_t)row0*SS + key]     = make_float2(e00, e01);
                    *(float2*)&wb[(size_t)(row0+8)*SS + key] = make_float2(e10, e11);
                    ap[ni>>1][(ni&1)*2    ] = pack_h2(e00, e01);
                    ap[ni>>1][(ni&1)*2 + 1] = pack_h2(e10, e11);
                }
            } else {
                #pragma unroll
                for (int ni = 0; ni < 4; ni++) {
                    int key = kpos0 + warpN*32 + ni*8 + 2*c;
                    float e00 = (key   <= row0  ) ? ex2f(S[ni][0] + L0) : 0.f;
                    float e01 = (key+1 <= row0  ) ? ex2f(S[ni][1] + L0) : 0.f;
                    float e10 = (key   <= row0+8) ? ex2f(S[ni][2] + L1) : 0.f;
                    float e11 = (key+1 <= row0+8) ? ex2f(S[ni][3] + L1) : 0.f;
                    *(float2*)&wb[(size_t)row0*SS + key]     = make_float2(e00, e01);
                    *(float2*)&wb[(size_t)(row0+8)*SS + key] = make_float2(e10, e11);
                    ap[ni>>1][(ni&1)*2    ] = pack_h2(e00, e01);
                    ap[ni>>1][(ni&1)*2 + 1] = pack_h2(e10, e11);
                }
            }

            #pragma unroll
            for (int ck = 0; ck < 2; ck++) {
                #pragma unroll
                for (int nib = 0; nib < 8; nib += 2) {
                    uint32_t bb4[4];
                    ldsm4t(bb4, sptr(&Vc[(warpN*32 + ck*16 + vR)*72
                                         + nib*8 + vC]));
                    mma_f16(O[nib    ], ap[ck], bb4);
                    mma_f16(O[nib + 1], ap[ck], bb4 + 2);
                }
            }
        }
    }

    __syncthreads();
    float* Osm = (float*)hsm;
    #pragma unroll 1
    for (int wn = 0; wn < 2; wn++) {
        if (warpN == wn) {
            int rr = warpM*16 + g;
            #pragma unroll
            for (int ni = 0; ni < 8; ni++) {
                int cc2 = ni*8 + 2*c;
                if (wn == 0) {
                    Osm[rr*65 + cc2]       = O[ni][0];
                    Osm[rr*65 + cc2 + 1]   = O[ni][1];
                    Osm[(rr+8)*65 + cc2]   = O[ni][2];
                    Osm[(rr+8)*65 + cc2+1] = O[ni][3];
                } else {
                    Osm[rr*65 + cc2]       += O[ni][0];
                    Osm[rr*65 + cc2 + 1]   += O[ni][1];
                    Osm[(rr+8)*65 + cc2]   += O[ni][2];
                    Osm[(rr+8)*65 + cc2+1] += O[ni][3];
                }
            }
        }
        __syncthreads();
    }

    {
        int b_ = bh >> 4, h = bh & 15;
        int row = t >> 2, cb = (t & 3) * 16;
        int s0 = q0 + row;
        uint32_t w[8];
        #pragma unroll
        for (int j = 0; j < 8; j++)
            w[j] = pack_h2(Osm[row*65 + cb + 2*j], Osm[row*65 + cb + 2*j + 1]);
        __half* dst = &g_apreh[((size_t)b_*SS + s0)*DD + h*HD + cb];
        *(uint4*)dst       = make_uint4(w[0], w[1], w[2], w[3]);
        *(uint4*)(dst + 8) = make_uint4(w[4], w[5], w[6], w[7]);
    }
}

extern "C" void kernel_launch(void* const* d_in, const int* in_sizes, int n_in,
                              void* d_out, int out_size)
{
    const float* hs = (const float*)d_in[0];
    const float* wq = (const float*)d_in[1];
    const float* bq = (const float*)d_in[2];
    const float* wk = (const float*)d_in[3];
    const float* bk = (const float*)d_in[4];
    const float* wv = (const float*)d_in[5];
    const float* bv = (const float*)d_in[6];
    const float* wc = (const float*)d_in[7];
    const float* bc = (const float*)d_in[8];

    float* out      = (float*)d_out;
    float* out_attn = out;
    float* out_w    = out + (size_t)BB*SS*DD;
    float* out_k    = out_w + (size_t)BB*HH*SS*SS;
    float* out_v    = out_k + (size_t)BB*HH*SS*HD;

    __half *hsh, *wt, *qh, *kh, *vh, *apreh;
    cudaGetSymbolAddress((void**)&hsh,   g_hsh);
    cudaGetSymbolAddress((void**)&wt,    g_wt);
    cudaGetSymbolAddress((void**)&qh,    g_qh);
    cudaGetSymbolAddress((void**)&kh,    g_kh);
    cudaGetSymbolAddress((void**)&vh,    g_vh);
    cudaGetSymbolAddress((void**)&apreh, g_apreh);

    cudaFuncSetAttribute(gemm_qkv,
                         cudaFuncAttributeMaxDynamicSharedMemorySize, GEMM_SMEM);
    cudaFuncSetAttribute(gemm_c,
                         cudaFuncAttributeMaxDynamicSharedMemorySize, GEMM_SMEM);
    cudaFuncSetAttribute(fattn,
                         cudaFuncAttributeMaxDynamicSharedMemorySize, FATTN_SMEM);

    conv_h<<<(MM*DD/4)/256, 256>>>(hs, hsh);
    tconv4_h<<<dim3(DD/32, DD/32, 4), 256>>>(wq, wk, wv, wc, wt);

    gemm_qkv<<<dim3(DD/128, MM/128, 3), 256, GEMM_SMEM>>>(
        hsh, wt, bq, bk, bv, out_k, out_v, qh, kh, vh);

    fattn<<<dim3(SS/64, BB*HH), 256, FATTN_SMEM>>>(kh, vh, out_w);

    gemm_c<<<dim3(DD/128, MM/128), 256, GEMM_SMEM>>>(
        apreh, wt + 3*(size_t)DD*DD, bc, out_attn);
}